// round 2
// baseline (speedup 1.0000x reference)
#include <cuda_runtime.h>
#include <math.h>

#define NVERT 2562
#define DEPTH 8
#define CDIM  512
#define NHEAD 8
#define HD    64
#define KNB   8
#define HIDD  2048
#define MTOK  (NVERT*DEPTH)   /* 20496 */
#define MPAD  20608           /* 161*128 */

// Zero-initialized device scratch (allocation-free per harness rules).
__device__ float g_xn [(size_t)MPAD*CDIM];      // LN output (reused for LN1 and LN2)
__device__ float g_qkv[(size_t)MPAD*3*CDIM];    // [q*8 | k | v]
__device__ float g_y  [(size_t)MPAD*CDIM];      // attention output
__device__ float g_x2 [(size_t)MPAD*CDIM];      // x + proj(y)
__device__ float g_h  [(size_t)MPAD*HIDD];      // gelu(fc1)

// ---------------------------------------------------------------------------
// LayerNorm: one block (128 threads) per token, 4 channels/thread via float4.
// ---------------------------------------------------------------------------
__global__ void ln_kernel(const float* __restrict__ x, const float* __restrict__ w,
                          const float* __restrict__ b, float* __restrict__ out) {
    int t = blockIdx.x;
    const float4* xr = (const float4*)(x + (size_t)t * CDIM);
    float4 v = xr[threadIdx.x];
    float s  = v.x + v.y + v.z + v.w;
    float s2 = v.x*v.x + v.y*v.y + v.z*v.z + v.w*v.w;
    #pragma unroll
    for (int o = 16; o; o >>= 1) {
        s  += __shfl_xor_sync(0xffffffffu, s,  o);
        s2 += __shfl_xor_sync(0xffffffffu, s2, o);
    }
    __shared__ float ss[4], ssq[4];
    int wid = threadIdx.x >> 5, lane = threadIdx.x & 31;
    if (lane == 0) { ss[wid] = s; ssq[wid] = s2; }
    __syncthreads();
    s  = ss[0] + ss[1] + ss[2] + ss[3];
    s2 = ssq[0] + ssq[1] + ssq[2] + ssq[3];
    float mean = s * (1.0f / CDIM);
    float var  = s2 * (1.0f / CDIM) - mean * mean;
    float rstd = rsqrtf(var + 1e-5f);
    float4 wv = ((const float4*)w)[threadIdx.x];
    float4 bv = ((const float4*)b)[threadIdx.x];
    float4 o;
    o.x = (v.x - mean) * rstd * wv.x + bv.x;
    o.y = (v.y - mean) * rstd * wv.y + bv.y;
    o.z = (v.z - mean) * rstd * wv.z + bv.z;
    o.w = (v.w - mean) * rstd * wv.w + bv.w;
    ((float4*)(out + (size_t)t * CDIM))[threadIdx.x] = o;
}

// ---------------------------------------------------------------------------
// SGEMM: C[M,N] = A[Mpad,K] @ W[N,K]^T (+ epilogue). 128x128x8 tile,
// 256 threads, 8x8 per thread (split 4+4 fragments), padded smem.
// EPI: 0 = bias + q-scale (store to padded scratch, cols<512 *= 8)
//      1 = bias + residual R[m] (store only m<M)
//      2 = bias + exact GELU (store to padded scratch)
// ---------------------------------------------------------------------------
template<int EPI>
__global__ void __launch_bounds__(256, 2)
sgemm_kernel(const float* __restrict__ A, const float* __restrict__ W,
             const float* __restrict__ bias, const float* __restrict__ R,
             float* __restrict__ C, int M, int N, int K) {
    __shared__ float As[8][132];
    __shared__ float Bs[8][132];

    const int tid   = threadIdx.x;
    const int mBase = blockIdx.x * 128;
    const int nBase = blockIdx.y * 128;
    const int lrow  = tid >> 1;
    const int lk    = (tid & 1) * 4;
    const int tx    = tid & 15;
    const int ty    = tid >> 4;

    const float* Aptr = A + (size_t)(mBase + lrow) * K + lk;
    const float* Wptr = W + (size_t)(nBase + lrow) * K + lk;

    float acc[8][8];
    #pragma unroll
    for (int i = 0; i < 8; i++)
        #pragma unroll
        for (int j = 0; j < 8; j++) acc[i][j] = 0.0f;

    for (int k0 = 0; k0 < K; k0 += 8) {
        float4 av = *(const float4*)(Aptr + k0);
        float4 wv = *(const float4*)(Wptr + k0);
        As[lk + 0][lrow] = av.x; As[lk + 1][lrow] = av.y;
        As[lk + 2][lrow] = av.z; As[lk + 3][lrow] = av.w;
        Bs[lk + 0][lrow] = wv.x; Bs[lk + 1][lrow] = wv.y;
        Bs[lk + 2][lrow] = wv.z; Bs[lk + 3][lrow] = wv.w;
        __syncthreads();
        #pragma unroll
        for (int kk = 0; kk < 8; kk++) {
            float a[8], b[8];
            *(float4*)(a)     = *(const float4*)&As[kk][ty * 4];
            *(float4*)(a + 4) = *(const float4*)&As[kk][64 + ty * 4];
            *(float4*)(b)     = *(const float4*)&Bs[kk][tx * 4];
            *(float4*)(b + 4) = *(const float4*)&Bs[kk][64 + tx * 4];
            #pragma unroll
            for (int i = 0; i < 8; i++)
                #pragma unroll
                for (int j = 0; j < 8; j++)
                    acc[i][j] += a[i] * b[j];
        }
        __syncthreads();
    }

    #pragma unroll
    for (int i = 0; i < 8; i++) {
        int rm = mBase + ((i < 4) ? (ty * 4 + i) : (64 + ty * 4 + i - 4));
        #pragma unroll
        for (int j = 0; j < 8; j++) {
            int cn = nBase + ((j < 4) ? (tx * 4 + j) : (64 + tx * 4 + j - 4));
            float v = acc[i][j] + bias[cn];
            if (EPI == 0) {
                if (cn < CDIM) v *= 8.0f;   // q * hd^0.5
                C[(size_t)rm * N + cn] = v;
            } else if (EPI == 1) {
                if (rm < M) C[(size_t)rm * N + cn] = v + R[(size_t)rm * N + cn];
            } else { // EPI == 2: exact GELU
                C[(size_t)rm * N + cn] = 0.5f * v * (1.0f + erff(v * 0.70710678118654752f));
            }
        }
    }
}

// ---------------------------------------------------------------------------
// Neighbor attention: one block per token (n,d). Warp = head. Lane owns 2
// channels. 8 neighbor dots via shuffle reduce, register softmax, weighted V.
// ---------------------------------------------------------------------------
__global__ void attn_kernel(const float* __restrict__ qkv, const int* __restrict__ which,
                            const int* __restrict__ mask, float* __restrict__ y) {
    int t = blockIdx.x;
    int n = t / DEPTH, d = t % DEPTH;
    int h = threadIdx.x >> 5;
    int lane = threadIdx.x & 31;

    float2 q = ((const float2*)(qkv + (size_t)t * (3 * CDIM) + h * HD))[lane];

    float sc[KNB];
    float2 vv[KNB];
    #pragma unroll
    for (int k = 0; k < KNB; k++) {
        int nb = which[n * KNB + k];
        const float* base = qkv + (size_t)(nb * DEPTH + d) * (3 * CDIM) + h * HD;
        float2 kv = ((const float2*)(base + CDIM))[lane];
        vv[k]     = ((const float2*)(base + 2 * CDIM))[lane];
        float dot = q.x * kv.x + q.y * kv.y;
        #pragma unroll
        for (int o = 16; o; o >>= 1) dot += __shfl_xor_sync(0xffffffffu, dot, o);
        sc[k] = (mask[n * KNB + k] > 0) ? dot : -1.0e9f;
    }

    float mx = sc[0];
    #pragma unroll
    for (int k = 1; k < KNB; k++) mx = fmaxf(mx, sc[k]);
    float wsum = 0.0f, w[KNB];
    #pragma unroll
    for (int k = 0; k < KNB; k++) { w[k] = __expf(sc[k] - mx); wsum += w[k]; }
    float inv = 1.0f / wsum;

    float2 acc = make_float2(0.0f, 0.0f);
    #pragma unroll
    for (int k = 0; k < KNB; k++) {
        acc.x += w[k] * vv[k].x;
        acc.y += w[k] * vv[k].y;
    }
    acc.x *= inv; acc.y *= inv;
    ((float2*)(y + (size_t)t * CDIM + h * HD))[lane] = acc;
}

// ---------------------------------------------------------------------------
extern "C" void kernel_launch(void* const* d_in, const int* in_sizes, int n_in,
                              void* d_out, int out_size) {
    const float* x      = (const float*)d_in[0];
    const int*   which  = (const int*)  d_in[1];
    const int*   mask   = (const int*)  d_in[2];
    const float* ln1_w  = (const float*)d_in[3];
    const float* ln1_b  = (const float*)d_in[4];
    const float* qkv_w  = (const float*)d_in[5];
    const float* qkv_b  = (const float*)d_in[6];
    const float* proj_w = (const float*)d_in[7];
    const float* proj_b = (const float*)d_in[8];
    const float* ln2_w  = (const float*)d_in[9];
    const float* ln2_b  = (const float*)d_in[10];
    const float* fc1_w  = (const float*)d_in[11];
    const float* fc1_b  = (const float*)d_in[12];
    const float* fc2_w  = (const float*)d_in[13];
    const float* fc2_b  = (const float*)d_in[14];
    float* out = (float*)d_out;

    float *p_xn, *p_qkv, *p_y, *p_x2, *p_h;
    cudaGetSymbolAddress((void**)&p_xn,  g_xn);
    cudaGetSymbolAddress((void**)&p_qkv, g_qkv);
    cudaGetSymbolAddress((void**)&p_y,   g_y);
    cudaGetSymbolAddress((void**)&p_x2,  g_x2);
    cudaGetSymbolAddress((void**)&p_h,   g_h);

    const int MT = 161;  // MPAD / 128

    // 1. LN1
    ln_kernel<<<MTOK, 128>>>(x, ln1_w, ln1_b, p_xn);
    // 2. QKV GEMM (+ q scale)
    sgemm_kernel<0><<<dim3(MT, 12), 256>>>(p_xn, qkv_w, qkv_b, nullptr, p_qkv,
                                           MTOK, 3 * CDIM, CDIM);
    // 3. Neighbor attention
    attn_kernel<<<MTOK, 256>>>(p_qkv, which, mask, p_y);
    // 4. proj + residual(x) -> x2
    sgemm_kernel<1><<<dim3(MT, 4), 256>>>(p_y, proj_w, proj_b, x, p_x2,
                                          MTOK, CDIM, CDIM);
    // 5. LN2
    ln_kernel<<<MTOK, 128>>>(p_x2, ln2_w, ln2_b, p_xn);
    // 6. fc1 + GELU
    sgemm_kernel<2><<<dim3(MT, 16), 256>>>(p_xn, fc1_w, fc1_b, nullptr, p_h,
                                           MTOK, HIDD, CDIM);
    // 7. fc2 + residual(x2) -> out
    sgemm_kernel<1><<<dim3(MT, 4), 256>>>(p_h, fc2_w, fc2_b, p_x2, out,
                                          MTOK, CDIM, HIDD);
    (void)in_sizes; (void)n_in; (void)out_size;
}

// round 5
// speedup vs baseline: 1.9677x; 1.9677x over previous
#include <cuda_runtime.h>
#include <cuda_bf16.h>
#include <math.h>
#include <stdint.h>

#define NVERT 2562
#define DEPTH 8
#define CDIM  512
#define NHEAD 8
#define HD    64
#define KNB   8
#define HIDD  2048
#define MTOK  (NVERT*DEPTH)   /* 20496 */
#define MPAD  20608           /* 161*128 */
#define MT    161

typedef __nv_bfloat16 bf16;
typedef __nv_bfloat162 bf162;

// fp32 scratch
__device__ float g_qkv[(size_t)MPAD*3*CDIM];
__device__ float g_x2 [(size_t)MPAD*CDIM];
// split-bf16 activation planes
__device__ bf16 g_xn_hi[(size_t)MPAD*CDIM];
__device__ bf16 g_xn_lo[(size_t)MPAD*CDIM];
__device__ bf16 g_y_hi [(size_t)MPAD*CDIM];
__device__ bf16 g_y_lo [(size_t)MPAD*CDIM];
__device__ bf16 g_h_hi [(size_t)MPAD*HIDD];
__device__ bf16 g_h_lo [(size_t)MPAD*HIDD];
// split-bf16 weight planes
__device__ bf16 g_wqkv_hi[(size_t)3*CDIM*CDIM];
__device__ bf16 g_wqkv_lo[(size_t)3*CDIM*CDIM];
__device__ bf16 g_wproj_hi[(size_t)CDIM*CDIM];
__device__ bf16 g_wproj_lo[(size_t)CDIM*CDIM];
__device__ bf16 g_wfc1_hi[(size_t)HIDD*CDIM];
__device__ bf16 g_wfc1_lo[(size_t)HIDD*CDIM];
__device__ bf16 g_wfc2_hi[(size_t)CDIM*HIDD];
__device__ bf16 g_wfc2_lo[(size_t)CDIM*HIDD];

__device__ __forceinline__ void bsplit(float x, bf16& hi, bf16& lo) {
    hi = __float2bfloat16_rn(x);
    lo = __float2bfloat16_rn(x - __bfloat162float(hi));
}

// ---------------------------------------------------------------------------
// Weight conversion: fp32 -> (hi, lo) bf16 planes.
// ---------------------------------------------------------------------------
__global__ void wcvt_kernel(const float4* __restrict__ w, bf162* __restrict__ hi,
                            bf162* __restrict__ lo, int n4) {
    int i = blockIdx.x * 256 + threadIdx.x;
    if (i < n4) {
        float4 v = w[i];
        bf16 h0,l0,h1,l1,h2,l2,h3,l3;
        bsplit(v.x,h0,l0); bsplit(v.y,h1,l1); bsplit(v.z,h2,l2); bsplit(v.w,h3,l3);
        hi[2*i]   = bf162(h0,h1); hi[2*i+1] = bf162(h2,h3);
        lo[2*i]   = bf162(l0,l1); lo[2*i+1] = bf162(l2,l3);
    }
}

// ---------------------------------------------------------------------------
// LayerNorm: one block (128 threads) per token; split-bf16 output.
// ---------------------------------------------------------------------------
__global__ void ln_kernel(const float* __restrict__ x, const float* __restrict__ w,
                          const float* __restrict__ b, bf162* __restrict__ ohi,
                          bf162* __restrict__ olo) {
    int t = blockIdx.x;
    const float4* xr = (const float4*)(x + (size_t)t * CDIM);
    float4 v = xr[threadIdx.x];
    float s  = v.x + v.y + v.z + v.w;
    float s2 = v.x*v.x + v.y*v.y + v.z*v.z + v.w*v.w;
    #pragma unroll
    for (int o = 16; o; o >>= 1) {
        s  += __shfl_xor_sync(0xffffffffu, s,  o);
        s2 += __shfl_xor_sync(0xffffffffu, s2, o);
    }
    __shared__ float ss[4], ssq[4];
    int wid = threadIdx.x >> 5, lane = threadIdx.x & 31;
    if (lane == 0) { ss[wid] = s; ssq[wid] = s2; }
    __syncthreads();
    s  = ss[0] + ss[1] + ss[2] + ss[3];
    s2 = ssq[0] + ssq[1] + ssq[2] + ssq[3];
    float mean = s * (1.0f / CDIM);
    float var  = s2 * (1.0f / CDIM) - mean * mean;
    float rstd = rsqrtf(var + 1e-5f);
    float4 wv = ((const float4*)w)[threadIdx.x];
    float4 bv = ((const float4*)b)[threadIdx.x];
    float o0 = (v.x - mean) * rstd * wv.x + bv.x;
    float o1 = (v.y - mean) * rstd * wv.y + bv.y;
    float o2 = (v.z - mean) * rstd * wv.z + bv.z;
    float o3 = (v.w - mean) * rstd * wv.w + bv.w;
    bf16 h0,l0,h1,l1,h2,l2,h3,l3;
    bsplit(o0,h0,l0); bsplit(o1,h1,l1); bsplit(o2,h2,l2); bsplit(o3,h3,l3);
    size_t base = (size_t)t * (CDIM/2) + 2*threadIdx.x;
    ohi[base]   = bf162(h0,h1); ohi[base+1] = bf162(h2,h3);
    olo[base]   = bf162(l0,l1); olo[base+1] = bf162(l2,l3);
}

// ---------------------------------------------------------------------------
// Split-bf16 tensor-core GEMM: C = A @ W^T with A = Ahi+Alo, W = Whi+Wlo,
// computing Ahi*Whi + Ahi*Wlo + Alo*Whi in fp32 accumulators.
// 128x128 tile, BK=32, 8 warps (2x4: 64x32 warp tile), double-buffered
// cp.async, smem rows padded to 40 bf16 (80B -> conflict-free ldmatrix).
// EPI: 0 = bias + q-scale -> fp32 C
//      1 = bias + residual R -> fp32 C (guard m<M)
//      2 = bias + exact GELU -> split-bf16 (Chi, Clo)
// ---------------------------------------------------------------------------
#define ROWB 80                       /* bytes per smem row (40 bf16) */
#define PLANE_ST 10240                /* bytes per plane stage: 128*80 */
#define AHI_B 0
#define ALO_B 20480
#define BHI_B 40960
#define BLO_B 61440
#define SMEM_BYTES 81920

__device__ __forceinline__ void cp_async16(uint32_t dst, const void* src) {
    asm volatile("cp.async.cg.shared.global [%0], [%1], 16;\n" :: "r"(dst), "l"(src));
}
#define LDSM4(r0,r1,r2,r3,addr) \
    asm volatile("ldmatrix.sync.aligned.m8n8.x4.shared.b16 {%0,%1,%2,%3}, [%4];" \
                 : "=r"(r0),"=r"(r1),"=r"(r2),"=r"(r3) : "r"(addr))
#define MMA_BF16(acc, a, b) \
    asm volatile("mma.sync.aligned.m16n8k16.row.col.f32.bf16.bf16.f32 " \
                 "{%0,%1,%2,%3}, {%4,%5,%6,%7}, {%8,%9}, {%0,%1,%2,%3};\n" \
                 : "+f"(acc[0]), "+f"(acc[1]), "+f"(acc[2]), "+f"(acc[3]) \
                 : "r"(a[0]), "r"(a[1]), "r"(a[2]), "r"(a[3]), "r"(b[0]), "r"(b[1]))

template<int EPI>
__global__ void __launch_bounds__(256)
mma_gemm(const bf16* __restrict__ Ahi, const bf16* __restrict__ Alo,
         const bf16* __restrict__ Whi, const bf16* __restrict__ Wlo,
         const float* __restrict__ bias, const float* __restrict__ R,
         float* __restrict__ C, bf16* __restrict__ Chi, bf16* __restrict__ Clo,
         int M, int N, int K) {
    extern __shared__ char sm[];
    uint32_t sb = (uint32_t)__cvta_generic_to_shared(sm);

    const int tid   = threadIdx.x;
    const int lane  = tid & 31;
    const int wid   = tid >> 5;
    const int wm    = wid & 1;
    const int wn    = wid >> 1;
    const int gid   = lane >> 2;
    const int tig   = lane & 3;
    const int mBase = blockIdx.x * 128;
    const int nBase = blockIdx.y * 128;
    const int nk    = K >> 5;

    // loader mapping: 2 chunk-pairs per row -> 8 cp.async/thread/stage
    const int lrow = tid >> 1;
    const int lcc  = (tid & 1) * 2;          // chunk index 0 or 2 (of 4)

    // ldmatrix per-lane address pattern
    const int lg = lane >> 3;                // 0..3
    const int lr = lane & 7;
    const int arow = lr + (lg & 1) * 8;      // row within 16-row tile
    const int akof = (lg >> 1) * 16;         // byte offset for k+8 half

    float acc[4][4][4];
    #pragma unroll
    for (int mi = 0; mi < 4; mi++)
        #pragma unroll
        for (int ni = 0; ni < 4; ni++)
            #pragma unroll
            for (int c = 0; c < 4; c++) acc[mi][ni][c] = 0.0f;

    auto stage_load = [&](int kt, int st) {
        int k0 = kt * 32;
        size_t ga = (size_t)(mBase + lrow) * K + k0 + lcc * 8;
        size_t gb = (size_t)(nBase + lrow) * K + k0 + lcc * 8;
        uint32_t d = sb + st * PLANE_ST + lrow * ROWB + lcc * 16;
        cp_async16(d + AHI_B,      Ahi + ga);
        cp_async16(d + AHI_B + 16, Ahi + ga + 8);
        cp_async16(d + ALO_B,      Alo + ga);
        cp_async16(d + ALO_B + 16, Alo + ga + 8);
        cp_async16(d + BHI_B,      Whi + gb);
        cp_async16(d + BHI_B + 16, Whi + gb + 8);
        cp_async16(d + BLO_B,      Wlo + gb);
        cp_async16(d + BLO_B + 16, Wlo + gb + 8);
        asm volatile("cp.async.commit_group;\n");
    };

    stage_load(0, 0);

    for (int kt = 0; kt < nk; kt++) {
        int st = kt & 1;
        if (kt + 1 < nk) {
            stage_load(kt + 1, (kt + 1) & 1);
            asm volatile("cp.async.wait_group 1;\n");
        } else {
            asm volatile("cp.async.wait_group 0;\n");
        }
        __syncthreads();

        uint32_t stb = sb + st * PLANE_ST;

        #pragma unroll
        for (int k16 = 0; k16 < 2; k16++) {
            uint32_t kb = k16 * 32 + akof;
            uint32_t ah[4][4], al[4][4], bh[4][2], bl[4][2];
            #pragma unroll
            for (int mi = 0; mi < 4; mi++) {
                uint32_t ra = stb + (uint32_t)(wm * 64 + mi * 16 + arow) * ROWB + kb;
                LDSM4(ah[mi][0], ah[mi][1], ah[mi][2], ah[mi][3], ra + AHI_B);
                LDSM4(al[mi][0], al[mi][1], al[mi][2], al[mi][3], ra + ALO_B);
            }
            #pragma unroll
            for (int nn = 0; nn < 2; nn++) {
                uint32_t rb = stb + (uint32_t)(wn * 32 + nn * 16 + arow) * ROWB + kb;
                uint32_t r0, r1, r2, r3;
                LDSM4(r0, r1, r2, r3, rb + BHI_B);
                bh[2*nn][0] = r0; bh[2*nn][1] = r2;
                bh[2*nn+1][0] = r1; bh[2*nn+1][1] = r3;
                LDSM4(r0, r1, r2, r3, rb + BLO_B);
                bl[2*nn][0] = r0; bl[2*nn][1] = r2;
                bl[2*nn+1][0] = r1; bl[2*nn+1][1] = r3;
            }
            #pragma unroll
            for (int mi = 0; mi < 4; mi++)
                #pragma unroll
                for (int ni = 0; ni < 4; ni++) {
                    MMA_BF16(acc[mi][ni], ah[mi], bh[ni]);
                    MMA_BF16(acc[mi][ni], ah[mi], bl[ni]);
                    MMA_BF16(acc[mi][ni], al[mi], bh[ni]);
                }
        }
        __syncthreads();
    }

    // epilogue
    #pragma unroll
    for (int mi = 0; mi < 4; mi++) {
        #pragma unroll
        for (int ni = 0; ni < 4; ni++) {
            int cn = nBase + wn * 32 + ni * 8 + 2 * tig;
            float b0 = bias[cn], b1 = bias[cn + 1];
            #pragma unroll
            for (int half = 0; half < 2; half++) {
                int rm = mBase + wm * 64 + mi * 16 + gid + half * 8;
                float v0 = acc[mi][ni][half * 2 + 0] + b0;
                float v1 = acc[mi][ni][half * 2 + 1] + b1;
                if (EPI == 0) {
                    if (cn < CDIM)     v0 *= 8.0f;
                    if (cn + 1 < CDIM) v1 *= 8.0f;
                    *(float2*)&C[(size_t)rm * N + cn] = make_float2(v0, v1);
                } else if (EPI == 1) {
                    if (rm < M) {
                        float2 r = *(const float2*)&R[(size_t)rm * N + cn];
                        *(float2*)&C[(size_t)rm * N + cn] = make_float2(v0 + r.x, v1 + r.y);
                    }
                } else {
                    v0 = 0.5f * v0 * (1.0f + erff(v0 * 0.70710678118654752f));
                    v1 = 0.5f * v1 * (1.0f + erff(v1 * 0.70710678118654752f));
                    bf16 h0,l0,h1,l1;
                    bsplit(v0,h0,l0); bsplit(v1,h1,l1);
                    *(bf162*)&Chi[(size_t)rm * N + cn] = bf162(h0,h1);
                    *(bf162*)&Clo[(size_t)rm * N + cn] = bf162(l0,l1);
                }
            }
        }
    }
}

// ---------------------------------------------------------------------------
// Neighbor attention: block per token, warp = head, lane = 2 channels.
// Output split-bf16 (feeds proj GEMM).
// ---------------------------------------------------------------------------
__global__ void attn_kernel(const float* __restrict__ qkv, const int* __restrict__ which,
                            const int* __restrict__ mask, bf162* __restrict__ yhi,
                            bf162* __restrict__ ylo) {
    int t = blockIdx.x;
    int n = t / DEPTH, d = t % DEPTH;
    int h = threadIdx.x >> 5;
    int lane = threadIdx.x & 31;

    float2 q = ((const float2*)(qkv + (size_t)t * (3 * CDIM) + h * HD))[lane];

    float sc[KNB];
    float2 vv[KNB];
    #pragma unroll
    for (int k = 0; k < KNB; k++) {
        int nb = which[n * KNB + k];
        const float* base = qkv + (size_t)(nb * DEPTH + d) * (3 * CDIM) + h * HD;
        float2 kv = ((const float2*)(base + CDIM))[lane];
        vv[k]     = ((const float2*)(base + 2 * CDIM))[lane];
        float dot = q.x * kv.x + q.y * kv.y;
        #pragma unroll
        for (int o = 16; o; o >>= 1) dot += __shfl_xor_sync(0xffffffffu, dot, o);
        sc[k] = (mask[n * KNB + k] > 0) ? dot : -1.0e9f;
    }

    float mx = sc[0];
    #pragma unroll
    for (int k = 1; k < KNB; k++) mx = fmaxf(mx, sc[k]);
    float wsum = 0.0f, w[KNB];
    #pragma unroll
    for (int k = 0; k < KNB; k++) { w[k] = __expf(sc[k] - mx); wsum += w[k]; }
    float inv = 1.0f / wsum;

    float2 acc = make_float2(0.0f, 0.0f);
    #pragma unroll
    for (int k = 0; k < KNB; k++) {
        acc.x += w[k] * vv[k].x;
        acc.y += w[k] * vv[k].y;
    }
    acc.x *= inv; acc.y *= inv;
    bf16 h0,l0,h1,l1;
    bsplit(acc.x,h0,l0); bsplit(acc.y,h1,l1);
    size_t base = (size_t)t * (CDIM/2) + (h * HD)/2 + lane;
    yhi[base] = bf162(h0,h1);
    ylo[base] = bf162(l0,l1);
}

// ---------------------------------------------------------------------------
extern "C" void kernel_launch(void* const* d_in, const int* in_sizes, int n_in,
                              void* d_out, int out_size) {
    const float* x      = (const float*)d_in[0];
    const int*   which  = (const int*)  d_in[1];
    const int*   mask   = (const int*)  d_in[2];
    const float* ln1_w  = (const float*)d_in[3];
    const float* ln1_b  = (const float*)d_in[4];
    const float* qkv_w  = (const float*)d_in[5];
    const float* qkv_b  = (const float*)d_in[6];
    const float* proj_w = (const float*)d_in[7];
    const float* proj_b = (const float*)d_in[8];
    const float* ln2_w  = (const float*)d_in[9];
    const float* ln2_b  = (const float*)d_in[10];
    const float* fc1_w  = (const float*)d_in[11];
    const float* fc1_b  = (const float*)d_in[12];
    const float* fc2_w  = (const float*)d_in[13];
    const float* fc2_b  = (const float*)d_in[14];
    float* out = (float*)d_out;

    float *p_qkv, *p_x2;
    bf16 *p_xnh, *p_xnl, *p_yh, *p_yl, *p_hh, *p_hl;
    bf16 *p_wqh, *p_wql, *p_wph, *p_wpl, *p_w1h, *p_w1l, *p_w2h, *p_w2l;
    cudaGetSymbolAddress((void**)&p_qkv, g_qkv);
    cudaGetSymbolAddress((void**)&p_x2,  g_x2);
    cudaGetSymbolAddress((void**)&p_xnh, g_xn_hi);
    cudaGetSymbolAddress((void**)&p_xnl, g_xn_lo);
    cudaGetSymbolAddress((void**)&p_yh,  g_y_hi);
    cudaGetSymbolAddress((void**)&p_yl,  g_y_lo);
    cudaGetSymbolAddress((void**)&p_hh,  g_h_hi);
    cudaGetSymbolAddress((void**)&p_hl,  g_h_lo);
    cudaGetSymbolAddress((void**)&p_wqh, g_wqkv_hi);
    cudaGetSymbolAddress((void**)&p_wql, g_wqkv_lo);
    cudaGetSymbolAddress((void**)&p_wph, g_wproj_hi);
    cudaGetSymbolAddress((void**)&p_wpl, g_wproj_lo);
    cudaGetSymbolAddress((void**)&p_w1h, g_wfc1_hi);
    cudaGetSymbolAddress((void**)&p_w1l, g_wfc1_lo);
    cudaGetSymbolAddress((void**)&p_w2h, g_wfc2_hi);
    cudaGetSymbolAddress((void**)&p_w2l, g_wfc2_lo);

    cudaFuncSetAttribute(mma_gemm<0>, cudaFuncAttributeMaxDynamicSharedMemorySize, SMEM_BYTES);
    cudaFuncSetAttribute(mma_gemm<1>, cudaFuncAttributeMaxDynamicSharedMemorySize, SMEM_BYTES);
    cudaFuncSetAttribute(mma_gemm<2>, cudaFuncAttributeMaxDynamicSharedMemorySize, SMEM_BYTES);

    // weight split
    wcvt_kernel<<<(3*CDIM*CDIM/4 + 255)/256, 256>>>((const float4*)qkv_w, (bf162*)p_wqh, (bf162*)p_wql, 3*CDIM*CDIM/4);
    wcvt_kernel<<<(CDIM*CDIM/4   + 255)/256, 256>>>((const float4*)proj_w,(bf162*)p_wph, (bf162*)p_wpl, CDIM*CDIM/4);
    wcvt_kernel<<<(HIDD*CDIM/4   + 255)/256, 256>>>((const float4*)fc1_w, (bf162*)p_w1h, (bf162*)p_w1l, HIDD*CDIM/4);
    wcvt_kernel<<<(CDIM*HIDD/4   + 255)/256, 256>>>((const float4*)fc2_w, (bf162*)p_w2h, (bf162*)p_w2l, CDIM*HIDD/4);

    // 1. LN1 -> split xn
    ln_kernel<<<MTOK, 128>>>(x, ln1_w, ln1_b, (bf162*)p_xnh, (bf162*)p_xnl);
    // 2. QKV GEMM (+ q scale) -> fp32 qkv
    mma_gemm<0><<<dim3(MT, 12), 256, SMEM_BYTES>>>(p_xnh, p_xnl, p_wqh, p_wql, qkv_b,
                                                   nullptr, p_qkv, nullptr, nullptr,
                                                   MTOK, 3 * CDIM, CDIM);
    // 3. attention -> split y
    attn_kernel<<<MTOK, 256>>>(p_qkv, which, mask, (bf162*)p_yh, (bf162*)p_yl);
    // 4. proj + residual(x) -> fp32 x2
    mma_gemm<1><<<dim3(MT, 4), 256, SMEM_BYTES>>>(p_yh, p_yl, p_wph, p_wpl, proj_b,
                                                  x, p_x2, nullptr, nullptr,
                                                  MTOK, CDIM, CDIM);
    // 5. LN2 -> split xn
    ln_kernel<<<MTOK, 128>>>(p_x2, ln2_w, ln2_b, (bf162*)p_xnh, (bf162*)p_xnl);
    // 6. fc1 + GELU -> split h
    mma_gemm<2><<<dim3(MT, 16), 256, SMEM_BYTES>>>(p_xnh, p_xnl, p_w1h, p_w1l, fc1_b,
                                                   nullptr, nullptr, p_hh, p_hl,
                                                   MTOK, HIDD, CDIM);
    // 7. fc2 + residual(x2) -> out
    mma_gemm<1><<<dim3(MT, 4), 256, SMEM_BYTES>>>(p_hh, p_hl, p_w2h, p_w2l, fc2_b,
                                                  p_x2, out, nullptr, nullptr,
                                                  MTOK, CDIM, HIDD);
    (void)in_sizes; (void)n_in; (void)out_size;
}

// round 8
// speedup vs baseline: 1.9700x; 1.0012x over previous
#include <cuda_runtime.h>
#include <cuda_bf16.h>
#include <math.h>
#include <stdint.h>

#define NVERT 2562
#define DEPTH 8
#define CDIM  512
#define NHEAD 8
#define HD    64
#define KNB   8
#define HIDD  2048
#define MTOK  (NVERT*DEPTH)   /* 20496 */
#define MPAD  20608           /* 161*128 */
#define MT    161

typedef __nv_bfloat16 bf16;
typedef __nv_bfloat162 bf162;

// fp32 scratch
__device__ float g_qkv[(size_t)MPAD*3*CDIM];
__device__ float g_x2 [(size_t)MPAD*CDIM];
// split-bf16 activation planes
__device__ bf16 g_xn_hi[(size_t)MPAD*CDIM];
__device__ bf16 g_xn_lo[(size_t)MPAD*CDIM];
__device__ bf16 g_y_hi [(size_t)MPAD*CDIM];
__device__ bf16 g_y_lo [(size_t)MPAD*CDIM];
__device__ bf16 g_h_hi [(size_t)MPAD*HIDD];
__device__ bf16 g_h_lo [(size_t)MPAD*HIDD];
// split-bf16 weight planes
__device__ bf16 g_wqkv_hi[(size_t)3*CDIM*CDIM];
__device__ bf16 g_wqkv_lo[(size_t)3*CDIM*CDIM];
__device__ bf16 g_wproj_hi[(size_t)CDIM*CDIM];
__device__ bf16 g_wproj_lo[(size_t)CDIM*CDIM];
__device__ bf16 g_wfc1_hi[(size_t)HIDD*CDIM];
__device__ bf16 g_wfc1_lo[(size_t)HIDD*CDIM];
__device__ bf16 g_wfc2_hi[(size_t)CDIM*HIDD];
__device__ bf16 g_wfc2_lo[(size_t)CDIM*HIDD];

__device__ __forceinline__ void bsplit(float x, bf16& hi, bf16& lo) {
    hi = __float2bfloat16_rn(x);
    lo = __float2bfloat16_rn(x - __bfloat162float(hi));
}

// ---------------------------------------------------------------------------
// Weight conversion: fp32 -> (hi, lo) bf16 planes.
// ---------------------------------------------------------------------------
__global__ void wcvt_kernel(const float4* __restrict__ w, bf162* __restrict__ hi,
                            bf162* __restrict__ lo, int n4) {
    int i = blockIdx.x * 256 + threadIdx.x;
    if (i < n4) {
        float4 v = w[i];
        bf16 h0,l0,h1,l1,h2,l2,h3,l3;
        bsplit(v.x,h0,l0); bsplit(v.y,h1,l1); bsplit(v.z,h2,l2); bsplit(v.w,h3,l3);
        hi[2*i]   = bf162(h0,h1); hi[2*i+1] = bf162(h2,h3);
        lo[2*i]   = bf162(l0,l1); lo[2*i+1] = bf162(l2,l3);
    }
}

// ---------------------------------------------------------------------------
// LayerNorm: one block (128 threads) per token; split-bf16 output.
// ---------------------------------------------------------------------------
__global__ void ln_kernel(const float* __restrict__ x, const float* __restrict__ w,
                          const float* __restrict__ b, bf162* __restrict__ ohi,
                          bf162* __restrict__ olo) {
    int t = blockIdx.x;
    const float4* xr = (const float4*)(x + (size_t)t * CDIM);
    float4 v = xr[threadIdx.x];
    float s  = v.x + v.y + v.z + v.w;
    float s2 = v.x*v.x + v.y*v.y + v.z*v.z + v.w*v.w;
    #pragma unroll
    for (int o = 16; o; o >>= 1) {
        s  += __shfl_xor_sync(0xffffffffu, s,  o);
        s2 += __shfl_xor_sync(0xffffffffu, s2, o);
    }
    __shared__ float ss[4], ssq[4];
    int wid = threadIdx.x >> 5, lane = threadIdx.x & 31;
    if (lane == 0) { ss[wid] = s; ssq[wid] = s2; }
    __syncthreads();
    s  = ss[0] + ss[1] + ss[2] + ss[3];
    s2 = ssq[0] + ssq[1] + ssq[2] + ssq[3];
    float mean = s * (1.0f / CDIM);
    float var  = s2 * (1.0f / CDIM) - mean * mean;
    float rstd = rsqrtf(var + 1e-5f);
    float4 wv = ((const float4*)w)[threadIdx.x];
    float4 bv = ((const float4*)b)[threadIdx.x];
    float o0 = (v.x - mean) * rstd * wv.x + bv.x;
    float o1 = (v.y - mean) * rstd * wv.y + bv.y;
    float o2 = (v.z - mean) * rstd * wv.z + bv.z;
    float o3 = (v.w - mean) * rstd * wv.w + bv.w;
    bf16 h0,l0,h1,l1,h2,l2,h3,l3;
    bsplit(o0,h0,l0); bsplit(o1,h1,l1); bsplit(o2,h2,l2); bsplit(o3,h3,l3);
    size_t base = (size_t)t * (CDIM/2) + 2*threadIdx.x;
    ohi[base]   = bf162(h0,h1); ohi[base+1] = bf162(h2,h3);
    olo[base]   = bf162(l0,l1); olo[base+1] = bf162(l2,l3);
}

// ---------------------------------------------------------------------------
// Split-bf16 tensor-core GEMM: C = A @ W^T with A = Ahi+Alo, W = Whi+Wlo,
// computing Ahi*Whi + Ahi*Wlo + Alo*Whi in fp32 accumulators.
// 128x128 tile, BK=32, 8 warps (2x4: 64x32 warp tile), double-buffered
// cp.async, smem rows padded to 40 bf16 (80B -> conflict-free ldmatrix).
// Inner loop phase-ordered (hh -> hl -> lh) to cap live registers so
// __launch_bounds__(256, 2) holds 2 CTAs/SM without spills.
// EPI: 0 = bias + q-scale -> fp32 C
//      1 = bias + residual R -> fp32 C (guard m<M)
//      2 = bias + exact GELU -> split-bf16 (Chi, Clo)
// ---------------------------------------------------------------------------
#define ROWB 80                       /* bytes per smem row (40 bf16) */
#define PLANE_ST 10240                /* bytes per plane stage: 128*80 */
#define AHI_B 0
#define ALO_B 20480
#define BHI_B 40960
#define BLO_B 61440
#define SMEM_BYTES 81920

__device__ __forceinline__ void cp_async16(uint32_t dst, const void* src) {
    asm volatile("cp.async.cg.shared.global [%0], [%1], 16;\n" :: "r"(dst), "l"(src));
}
#define LDSM4(r0,r1,r2,r3,addr) \
    asm volatile("ldmatrix.sync.aligned.m8n8.x4.shared.b16 {%0,%1,%2,%3}, [%4];" \
                 : "=r"(r0),"=r"(r1),"=r"(r2),"=r"(r3) : "r"(addr))
#define MMA_BF16(acc, a, b) \
    asm volatile("mma.sync.aligned.m16n8k16.row.col.f32.bf16.bf16.f32 " \
                 "{%0,%1,%2,%3}, {%4,%5,%6,%7}, {%8,%9}, {%0,%1,%2,%3};\n" \
                 : "+f"(acc[0]), "+f"(acc[1]), "+f"(acc[2]), "+f"(acc[3]) \
                 : "r"(a[0]), "r"(a[1]), "r"(a[2]), "r"(a[3]), "r"(b[0]), "r"(b[1]))

template<int EPI>
__global__ void __launch_bounds__(256, 2)
mma_gemm(const bf16* __restrict__ Ahi, const bf16* __restrict__ Alo,
         const bf16* __restrict__ Whi, const bf16* __restrict__ Wlo,
         const float* __restrict__ bias, const float* __restrict__ R,
         float* __restrict__ C, bf16* __restrict__ Chi, bf16* __restrict__ Clo,
         int M, int N, int K) {
    extern __shared__ char sm[];
    uint32_t sb = (uint32_t)__cvta_generic_to_shared(sm);

    const int tid   = threadIdx.x;
    const int lane  = tid & 31;
    const int wid   = tid >> 5;
    const int wm    = wid & 1;
    const int wn    = wid >> 1;
    const int gid   = lane >> 2;
    const int tig   = lane & 3;
    const int mBase = blockIdx.x * 128;
    const int nBase = blockIdx.y * 128;
    const int nk    = K >> 5;

    // loader mapping: 2 chunk-pairs per row -> 8 cp.async/thread/stage
    const int lrow = tid >> 1;
    const int lcc  = (tid & 1) * 2;          // chunk index 0 or 2 (of 4)

    // ldmatrix per-lane address pattern
    const int lg = lane >> 3;                // 0..3
    const int lr = lane & 7;
    const int arow = lr + (lg & 1) * 8;      // row within 16-row tile
    const int akof = (lg >> 1) * 16;         // byte offset for k+8 half

    float acc[4][4][4];
    #pragma unroll
    for (int mi = 0; mi < 4; mi++)
        #pragma unroll
        for (int ni = 0; ni < 4; ni++)
            #pragma unroll
            for (int c = 0; c < 4; c++) acc[mi][ni][c] = 0.0f;

    auto stage_load = [&](int kt, int st) {
        int k0 = kt * 32;
        size_t ga = (size_t)(mBase + lrow) * K + k0 + lcc * 8;
        size_t gb = (size_t)(nBase + lrow) * K + k0 + lcc * 8;
        uint32_t d = sb + st * PLANE_ST + lrow * ROWB + lcc * 16;
        cp_async16(d + AHI_B,      Ahi + ga);
        cp_async16(d + AHI_B + 16, Ahi + ga + 8);
        cp_async16(d + ALO_B,      Alo + ga);
        cp_async16(d + ALO_B + 16, Alo + ga + 8);
        cp_async16(d + BHI_B,      Whi + gb);
        cp_async16(d + BHI_B + 16, Whi + gb + 8);
        cp_async16(d + BLO_B,      Wlo + gb);
        cp_async16(d + BLO_B + 16, Wlo + gb + 8);
        asm volatile("cp.async.commit_group;\n");
    };

    stage_load(0, 0);

    for (int kt = 0; kt < nk; kt++) {
        int st = kt & 1;
        if (kt + 1 < nk) {
            stage_load(kt + 1, (kt + 1) & 1);
            asm volatile("cp.async.wait_group 1;\n");
        } else {
            asm volatile("cp.async.wait_group 0;\n");
        }
        __syncthreads();

        uint32_t stb = sb + st * PLANE_ST;

        #pragma unroll
        for (int k16 = 0; k16 < 2; k16++) {
            uint32_t kb = k16 * 32 + akof;

            // phase 1: hi*hi
            uint32_t ah[4][4], bh[4][2];
            #pragma unroll
            for (int mi = 0; mi < 4; mi++) {
                uint32_t ra = stb + (uint32_t)(wm * 64 + mi * 16 + arow) * ROWB + kb;
                LDSM4(ah[mi][0], ah[mi][1], ah[mi][2], ah[mi][3], ra + AHI_B);
            }
            #pragma unroll
            for (int nn = 0; nn < 2; nn++) {
                uint32_t rb = stb + (uint32_t)(wn * 32 + nn * 16 + arow) * ROWB + kb;
                uint32_t r0, r1, r2, r3;
                LDSM4(r0, r1, r2, r3, rb + BHI_B);
                bh[2*nn][0] = r0; bh[2*nn][1] = r2;
                bh[2*nn+1][0] = r1; bh[2*nn+1][1] = r3;
            }
            #pragma unroll
            for (int mi = 0; mi < 4; mi++)
                #pragma unroll
                for (int ni = 0; ni < 4; ni++)
                    MMA_BF16(acc[mi][ni], ah[mi], bh[ni]);

            // phase 2: hi*lo (bl lives only here)
            {
                uint32_t bl[4][2];
                #pragma unroll
                for (int nn = 0; nn < 2; nn++) {
                    uint32_t rb = stb + (uint32_t)(wn * 32 + nn * 16 + arow) * ROWB + kb;
                    uint32_t r0, r1, r2, r3;
                    LDSM4(r0, r1, r2, r3, rb + BLO_B);
                    bl[2*nn][0] = r0; bl[2*nn][1] = r2;
                    bl[2*nn+1][0] = r1; bl[2*nn+1][1] = r3;
                }
                #pragma unroll
                for (int mi = 0; mi < 4; mi++)
                    #pragma unroll
                    for (int ni = 0; ni < 4; ni++)
                        MMA_BF16(acc[mi][ni], ah[mi], bl[ni]);
            }

            // phase 3: lo*hi (al replaces ah's role; ah dead after overwrite order)
            {
                uint32_t al[4][4];
                #pragma unroll
                for (int mi = 0; mi < 4; mi++) {
                    uint32_t ra = stb + (uint32_t)(wm * 64 + mi * 16 + arow) * ROWB + kb;
                    LDSM4(al[mi][0], al[mi][1], al[mi][2], al[mi][3], ra + ALO_B);
                }
                #pragma unroll
                for (int mi = 0; mi < 4; mi++)
                    #pragma unroll
                    for (int ni = 0; ni < 4; ni++)
                        MMA_BF16(acc[mi][ni], al[mi], bh[ni]);
            }
        }
        __syncthreads();
    }

    // epilogue
    #pragma unroll
    for (int mi = 0; mi < 4; mi++) {
        #pragma unroll
        for (int ni = 0; ni < 4; ni++) {
            int cn = nBase + wn * 32 + ni * 8 + 2 * tig;
            float b0 = bias[cn], b1 = bias[cn + 1];
            #pragma unroll
            for (int half = 0; half < 2; half++) {
                int rm = mBase + wm * 64 + mi * 16 + gid + half * 8;
                float v0 = acc[mi][ni][half * 2 + 0] + b0;
                float v1 = acc[mi][ni][half * 2 + 1] + b1;
                if (EPI == 0) {
                    if (cn < CDIM)     v0 *= 8.0f;
                    if (cn + 1 < CDIM) v1 *= 8.0f;
                    *(float2*)&C[(size_t)rm * N + cn] = make_float2(v0, v1);
                } else if (EPI == 1) {
                    if (rm < M) {
                        float2 r = *(const float2*)&R[(size_t)rm * N + cn];
                        *(float2*)&C[(size_t)rm * N + cn] = make_float2(v0 + r.x, v1 + r.y);
                    }
                } else {
                    v0 = 0.5f * v0 * (1.0f + erff(v0 * 0.70710678118654752f));
                    v1 = 0.5f * v1 * (1.0f + erff(v1 * 0.70710678118654752f));
                    bf16 h0,l0,h1,l1;
                    bsplit(v0,h0,l0); bsplit(v1,h1,l1);
                    *(bf162*)&Chi[(size_t)rm * N + cn] = bf162(h0,h1);
                    *(bf162*)&Clo[(size_t)rm * N + cn] = bf162(l0,l1);
                }
            }
        }
    }
}

// ---------------------------------------------------------------------------
// Neighbor attention: block per token, warp = head, lane = 2 channels.
// Output split-bf16 (feeds proj GEMM).
// ---------------------------------------------------------------------------
__global__ void attn_kernel(const float* __restrict__ qkv, const int* __restrict__ which,
                            const int* __restrict__ mask, bf162* __restrict__ yhi,
                            bf162* __restrict__ ylo) {
    int t = blockIdx.x;
    int n = t / DEPTH, d = t % DEPTH;
    int h = threadIdx.x >> 5;
    int lane = threadIdx.x & 31;

    float2 q = ((const float2*)(qkv + (size_t)t * (3 * CDIM) + h * HD))[lane];

    float sc[KNB];
    float2 vv[KNB];
    #pragma unroll
    for (int k = 0; k < KNB; k++) {
        int nb = which[n * KNB + k];
        const float* base = qkv + (size_t)(nb * DEPTH + d) * (3 * CDIM) + h * HD;
        float2 kv = ((const float2*)(base + CDIM))[lane];
        vv[k]     = ((const float2*)(base + 2 * CDIM))[lane];
        float dot = q.x * kv.x + q.y * kv.y;
        #pragma unroll
        for (int o = 16; o; o >>= 1) dot += __shfl_xor_sync(0xffffffffu, dot, o);
        sc[k] = (mask[n * KNB + k] > 0) ? dot : -1.0e9f;
    }

    float mx = sc[0];
    #pragma unroll
    for (int k = 1; k < KNB; k++) mx = fmaxf(mx, sc[k]);
    float wsum = 0.0f, w[KNB];
    #pragma unroll
    for (int k = 0; k < KNB; k++) { w[k] = __expf(sc[k] - mx); wsum += w[k]; }
    float inv = 1.0f / wsum;

    float2 acc = make_float2(0.0f, 0.0f);
    #pragma unroll
    for (int k = 0; k < KNB; k++) {
        acc.x += w[k] * vv[k].x;
        acc.y += w[k] * vv[k].y;
    }
    acc.x *= inv; acc.y *= inv;
    bf16 h0,l0,h1,l1;
    bsplit(acc.x,h0,l0); bsplit(acc.y,h1,l1);
    size_t base = (size_t)t * (CDIM/2) + (h * HD)/2 + lane;
    yhi[base] = bf162(h0,h1);
    ylo[base] = bf162(l0,l1);
}

// ---------------------------------------------------------------------------
extern "C" void kernel_launch(void* const* d_in, const int* in_sizes, int n_in,
                              void* d_out, int out_size) {
    const float* x      = (const float*)d_in[0];
    const int*   which  = (const int*)  d_in[1];
    const int*   mask   = (const int*)  d_in[2];
    const float* ln1_w  = (const float*)d_in[3];
    const float* ln1_b  = (const float*)d_in[4];
    const float* qkv_w  = (const float*)d_in[5];
    const float* qkv_b  = (const float*)d_in[6];
    const float* proj_w = (const float*)d_in[7];
    const float* proj_b = (const float*)d_in[8];
    const float* ln2_w  = (const float*)d_in[9];
    const float* ln2_b  = (const float*)d_in[10];
    const float* fc1_w  = (const float*)d_in[11];
    const float* fc1_b  = (const float*)d_in[12];
    const float* fc2_w  = (const float*)d_in[13];
    const float* fc2_b  = (const float*)d_in[14];
    float* out = (float*)d_out;

    float *p_qkv, *p_x2;
    bf16 *p_xnh, *p_xnl, *p_yh, *p_yl, *p_hh, *p_hl;
    bf16 *p_wqh, *p_wql, *p_wph, *p_wpl, *p_w1h, *p_w1l, *p_w2h, *p_w2l;
    cudaGetSymbolAddress((void**)&p_qkv, g_qkv);
    cudaGetSymbolAddress((void**)&p_x2,  g_x2);
    cudaGetSymbolAddress((void**)&p_xnh, g_xn_hi);
    cudaGetSymbolAddress((void**)&p_xnl, g_xn_lo);
    cudaGetSymbolAddress((void**)&p_yh,  g_y_hi);
    cudaGetSymbolAddress((void**)&p_yl,  g_y_lo);
    cudaGetSymbolAddress((void**)&p_hh,  g_h_hi);
    cudaGetSymbolAddress((void**)&p_hl,  g_h_lo);
    cudaGetSymbolAddress((void**)&p_wqh, g_wqkv_hi);
    cudaGetSymbolAddress((void**)&p_wql, g_wqkv_lo);
    cudaGetSymbolAddress((void**)&p_wph, g_wproj_hi);
    cudaGetSymbolAddress((void**)&p_wpl, g_wproj_lo);
    cudaGetSymbolAddress((void**)&p_w1h, g_wfc1_hi);
    cudaGetSymbolAddress((void**)&p_w1l, g_wfc1_lo);
    cudaGetSymbolAddress((void**)&p_w2h, g_wfc2_hi);
    cudaGetSymbolAddress((void**)&p_w2l, g_wfc2_lo);

    cudaFuncSetAttribute(mma_gemm<0>, cudaFuncAttributeMaxDynamicSharedMemorySize, SMEM_BYTES);
    cudaFuncSetAttribute(mma_gemm<1>, cudaFuncAttributeMaxDynamicSharedMemorySize, SMEM_BYTES);
    cudaFuncSetAttribute(mma_gemm<2>, cudaFuncAttributeMaxDynamicSharedMemorySize, SMEM_BYTES);

    // weight split
    wcvt_kernel<<<(3*CDIM*CDIM/4 + 255)/256, 256>>>((const float4*)qkv_w, (bf162*)p_wqh, (bf162*)p_wql, 3*CDIM*CDIM/4);
    wcvt_kernel<<<(CDIM*CDIM/4   + 255)/256, 256>>>((const float4*)proj_w,(bf162*)p_wph, (bf162*)p_wpl, CDIM*CDIM/4);
    wcvt_kernel<<<(HIDD*CDIM/4   + 255)/256, 256>>>((const float4*)fc1_w, (bf162*)p_w1h, (bf162*)p_w1l, HIDD*CDIM/4);
    wcvt_kernel<<<(CDIM*HIDD/4   + 255)/256, 256>>>((const float4*)fc2_w, (bf162*)p_w2h, (bf162*)p_w2l, CDIM*HIDD/4);

    // 1. LN1 -> split xn
    ln_kernel<<<MTOK, 128>>>(x, ln1_w, ln1_b, (bf162*)p_xnh, (bf162*)p_xnl);
    // 2. QKV GEMM (+ q scale) -> fp32 qkv
    mma_gemm<0><<<dim3(MT, 12), 256, SMEM_BYTES>>>(p_xnh, p_xnl, p_wqh, p_wql, qkv_b,
                                                   nullptr, p_qkv, nullptr, nullptr,
                                                   MTOK, 3 * CDIM, CDIM);
    // 3. attention -> split y
    attn_kernel<<<MTOK, 256>>>(p_qkv, which, mask, (bf162*)p_yh, (bf162*)p_yl);
    // 4. proj + residual(x) -> fp32 x2
    mma_gemm<1><<<dim3(MT, 4), 256, SMEM_BYTES>>>(p_yh, p_yl, p_wph, p_wpl, proj_b,
                                                  x, p_x2, nullptr, nullptr,
                                                  MTOK, CDIM, CDIM);
    // 5. LN2 -> split xn
    ln_kernel<<<MTOK, 128>>>(p_x2, ln2_w, ln2_b, (bf162*)p_xnh, (bf162*)p_xnl);
    // 6. fc1 + GELU -> split h
    mma_gemm<2><<<dim3(MT, 16), 256, SMEM_BYTES>>>(p_xnh, p_xnl, p_w1h, p_w1l, fc1_b,
                                                   nullptr, nullptr, p_hh, p_hl,
                                                   MTOK, HIDD, CDIM);
    // 7. fc2 + residual(x2) -> out
    mma_gemm<1><<<dim3(MT, 4), 256, SMEM_BYTES>>>(p_hh, p_hl, p_w2h, p_w2l, fc2_b,
                                                  p_x2, out, nullptr, nullptr,
                                                  MTOK, CDIM, HIDD);
    (void)in_sizes; (void)n_in; (void)out_size;
}

// round 10
// speedup vs baseline: 2.8858x; 1.4649x over previous
#include <cuda_runtime.h>
#include <math.h>
#include <stdint.h>

#define NVERT 2562
#define DEPTH 8
#define CDIM  512
#define NHEAD 8
#define HD    64
#define KNB   8
#define HIDD  2048
#define MTOK  (NVERT*DEPTH)   /* 20496 */
#define MPAD  20608           /* 161*128 */
#define MT    161

// fp32 scratch
__device__ float g_qkv[(size_t)MPAD*3*CDIM];
__device__ float g_x2 [(size_t)MPAD*CDIM];
// int8 activation planes (hi, lo)
__device__ int8_t g_xn_h[(size_t)MPAD*CDIM];
__device__ int8_t g_xn_l[(size_t)MPAD*CDIM];
__device__ int8_t g_y_h [(size_t)MPAD*CDIM];
__device__ int8_t g_y_l [(size_t)MPAD*CDIM];
__device__ int8_t g_h_h [(size_t)MPAD*HIDD];
__device__ int8_t g_h_l [(size_t)MPAD*HIDD];
// per-row activation scales (zero-init -> padded rows contribute 0)
__device__ float g_sa1[MPAD];
__device__ float g_sa2[MPAD];
// int8 weight planes + per-row scales
__device__ int8_t g_wqkv_h[(size_t)3*CDIM*CDIM];
__device__ int8_t g_wqkv_l[(size_t)3*CDIM*CDIM];
__device__ int8_t g_wproj_h[(size_t)CDIM*CDIM];
__device__ int8_t g_wproj_l[(size_t)CDIM*CDIM];
__device__ int8_t g_wfc1_h[(size_t)HIDD*CDIM];
__device__ int8_t g_wfc1_l[(size_t)HIDD*CDIM];
__device__ int8_t g_wfc2_h[(size_t)CDIM*HIDD];
__device__ int8_t g_wfc2_l[(size_t)CDIM*HIDD];
__device__ float g_swqkv[3*CDIM];
__device__ float g_swproj[CDIM];
__device__ float g_swfc1[HIDD];
__device__ float g_swfc2[CDIM];

#define S_H 6.0f   /* fixed scale for GELU outputs */

// x ~= s/127 * (h + l/254)
__device__ __forceinline__ void isplit(float x, float inv /* =127/s */,
                                       int8_t& h, int8_t& l) {
    float q = fminf(fmaxf(x * inv, -127.0f), 127.0f);
    int hi = __float2int_rn(q);
    int lo = __float2int_rn((q - (float)hi) * 254.0f);
    h = (int8_t)hi; l = (int8_t)lo;
}

// ---------------------------------------------------------------------------
// Weight quantization: one block (128 thr) per output row; per-row scale.
// ---------------------------------------------------------------------------
__global__ void wq_kernel(const float* __restrict__ w, int8_t* __restrict__ h,
                          int8_t* __restrict__ l, float* __restrict__ sw, int K) {
    int row = blockIdx.x, tid = threadIdx.x;
    const float* wr = w + (size_t)row * K;
    float m = 0.0f;
    for (int j = tid; j < K; j += 128) m = fmaxf(m, fabsf(wr[j]));
    #pragma unroll
    for (int o = 16; o; o >>= 1) m = fmaxf(m, __shfl_xor_sync(0xffffffffu, m, o));
    __shared__ float sm4[4];
    if ((tid & 31) == 0) sm4[tid >> 5] = m;
    __syncthreads();
    m = fmaxf(fmaxf(sm4[0], sm4[1]), fmaxf(sm4[2], sm4[3]));
    float s = fmaxf(m, 1e-20f), inv = 127.0f / s;
    if (tid == 0) sw[row] = s;
    for (int j = tid; j < K; j += 128) {
        int8_t hh, ll; isplit(wr[j], inv, hh, ll);
        h[(size_t)row * K + j] = hh;
        l[(size_t)row * K + j] = ll;
    }
}

// ---------------------------------------------------------------------------
// LayerNorm: block (128 thr) per token; int8-split output + per-row scale.
// ---------------------------------------------------------------------------
__global__ void ln_kernel(const float* __restrict__ x, const float* __restrict__ w,
                          const float* __restrict__ b, int8_t* __restrict__ oh,
                          int8_t* __restrict__ ol, float* __restrict__ sa) {
    int t = blockIdx.x;
    const float4* xr = (const float4*)(x + (size_t)t * CDIM);
    float4 v = xr[threadIdx.x];
    float s  = v.x + v.y + v.z + v.w;
    float s2 = v.x*v.x + v.y*v.y + v.z*v.z + v.w*v.w;
    #pragma unroll
    for (int o = 16; o; o >>= 1) {
        s  += __shfl_xor_sync(0xffffffffu, s,  o);
        s2 += __shfl_xor_sync(0xffffffffu, s2, o);
    }
    __shared__ float ss[4], ssq[4], smx[4];
    int wid = threadIdx.x >> 5, lane = threadIdx.x & 31;
    if (lane == 0) { ss[wid] = s; ssq[wid] = s2; }
    __syncthreads();
    s  = ss[0] + ss[1] + ss[2] + ss[3];
    s2 = ssq[0] + ssq[1] + ssq[2] + ssq[3];
    float mean = s * (1.0f / CDIM);
    float var  = s2 * (1.0f / CDIM) - mean * mean;
    float rstd = rsqrtf(var + 1e-5f);
    float4 wv = ((const float4*)w)[threadIdx.x];
    float4 bv = ((const float4*)b)[threadIdx.x];
    float o0 = (v.x - mean) * rstd * wv.x + bv.x;
    float o1 = (v.y - mean) * rstd * wv.y + bv.y;
    float o2 = (v.z - mean) * rstd * wv.z + bv.z;
    float o3 = (v.w - mean) * rstd * wv.w + bv.w;
    float mx = fmaxf(fmaxf(fabsf(o0), fabsf(o1)), fmaxf(fabsf(o2), fabsf(o3)));
    #pragma unroll
    for (int o = 16; o; o >>= 1) mx = fmaxf(mx, __shfl_xor_sync(0xffffffffu, mx, o));
    if (lane == 0) smx[wid] = mx;
    __syncthreads();
    mx = fmaxf(fmaxf(smx[0], smx[1]), fmaxf(smx[2], smx[3]));
    float sc = fmaxf(mx, 1e-20f), inv = 127.0f / sc;
    int8_t h0,l0,h1,l1,h2,l2,h3,l3;
    isplit(o0, inv, h0, l0); isplit(o1, inv, h1, l1);
    isplit(o2, inv, h2, l2); isplit(o3, inv, h3, l3);
    char4 hc; hc.x=h0; hc.y=h1; hc.z=h2; hc.w=h3;
    char4 lc; lc.x=l0; lc.y=l1; lc.z=l2; lc.w=l3;
    ((char4*)(oh + (size_t)t * CDIM))[threadIdx.x] = hc;
    ((char4*)(ol + (size_t)t * CDIM))[threadIdx.x] = lc;
    if (threadIdx.x == 0) sa[t] = sc;
}

// ---------------------------------------------------------------------------
// Split-int8 IMMA GEMM: C = A @ W^T with A,W each 2-plane int8.
// acc_hh and acc_cross in int32 (exact); C = sa*sw/16129*(hh + cross/254).
// 128x128 tile, stage depth 64 int8 (4 planes, row pitch 80B), double-buffered
// cp.async, 8 warps 2x4 (64x32 warp tile).
// EPI: 0 = bias + q-scale -> fp32 C
//      1 = bias + residual R -> fp32 C (guard m<M)
//      2 = bias + exact GELU -> int8-split (Ch, Cl) with fixed scale S_H
// ---------------------------------------------------------------------------
#define ROWB 80
#define PLANE_ST 10240
#define AHI_B 0
#define ALO_B 20480
#define BHI_B 40960
#define BLO_B 61440
#define SMEM_BYTES 81920

__device__ __forceinline__ void cp_async16(uint32_t dst, const void* src) {
    asm volatile("cp.async.cg.shared.global [%0], [%1], 16;\n" :: "r"(dst), "l"(src));
}
#define LDSM4(r0,r1,r2,r3,addr) \
    asm volatile("ldmatrix.sync.aligned.m8n8.x4.shared.b16 {%0,%1,%2,%3}, [%4];" \
                 : "=r"(r0),"=r"(r1),"=r"(r2),"=r"(r3) : "r"(addr))
#define MMA_S8(c, a, b) \
    asm volatile("mma.sync.aligned.m16n8k32.row.col.satfinite.s32.s8.s8.s32 " \
                 "{%0,%1,%2,%3}, {%4,%5,%6,%7}, {%8,%9}, {%0,%1,%2,%3};\n" \
                 : "+r"((c)[0]), "+r"((c)[1]), "+r"((c)[2]), "+r"((c)[3]) \
                 : "r"((a)[0]), "r"((a)[1]), "r"((a)[2]), "r"((a)[3]), \
                   "r"((b)[0]), "r"((b)[1]))

template<int EPI>
__global__ void __launch_bounds__(256)
imma_gemm(const int8_t* __restrict__ Ah, const int8_t* __restrict__ Al,
          const int8_t* __restrict__ Wh, const int8_t* __restrict__ Wl,
          const float* __restrict__ Sa, float saFixed,
          const float* __restrict__ Sw,
          const float* __restrict__ bias, const float* __restrict__ R,
          float* __restrict__ C, int8_t* __restrict__ Ch, int8_t* __restrict__ Cl,
          int M, int N, int K) {
    extern __shared__ char sm[];
    uint32_t sb = (uint32_t)__cvta_generic_to_shared(sm);

    const int tid   = threadIdx.x;
    const int lane  = tid & 31;
    const int wid   = tid >> 5;
    const int wm    = wid & 1;
    const int wn    = wid >> 1;
    const int gid   = lane >> 2;
    const int tig   = lane & 3;
    const int mBase = blockIdx.x * 128;
    const int nBase = blockIdx.y * 128;
    const int nk    = K >> 6;                // stages of 64 int8

    const int lrow = tid >> 1;
    const int lcc  = (tid & 1) * 2;          // 16B chunk 0 or 2 (of 4)

    const int lg = lane >> 3;
    const int lr = lane & 7;
    const int arow = lr + (lg & 1) * 8;
    const int akof = (lg >> 1) * 16;         // byte half within 32B k32 chunk

    int acc_h[4][4][4], acc_x[4][4][4];
    #pragma unroll
    for (int mi = 0; mi < 4; mi++)
        #pragma unroll
        for (int ni = 0; ni < 4; ni++)
            #pragma unroll
            for (int c = 0; c < 4; c++) { acc_h[mi][ni][c] = 0; acc_x[mi][ni][c] = 0; }

    auto stage_load = [&](int kt, int st) {
        int k0 = kt * 64;
        size_t ga = (size_t)(mBase + lrow) * K + k0 + lcc * 16;
        size_t gb = (size_t)(nBase + lrow) * K + k0 + lcc * 16;
        uint32_t d = sb + st * PLANE_ST + lrow * ROWB + lcc * 16;
        cp_async16(d + AHI_B,      Ah + ga);
        cp_async16(d + AHI_B + 16, Ah + ga + 16);
        cp_async16(d + ALO_B,      Al + ga);
        cp_async16(d + ALO_B + 16, Al + ga + 16);
        cp_async16(d + BHI_B,      Wh + gb);
        cp_async16(d + BHI_B + 16, Wh + gb + 16);
        cp_async16(d + BLO_B,      Wl + gb);
        cp_async16(d + BLO_B + 16, Wl + gb + 16);
        asm volatile("cp.async.commit_group;\n");
    };

    stage_load(0, 0);

    for (int kt = 0; kt < nk; kt++) {
        int st = kt & 1;
        if (kt + 1 < nk) {
            stage_load(kt + 1, (kt + 1) & 1);
            asm volatile("cp.async.wait_group 1;\n");
        } else {
            asm volatile("cp.async.wait_group 0;\n");
        }
        __syncthreads();

        uint32_t stb = sb + st * PLANE_ST;

        #pragma unroll
        for (int k32 = 0; k32 < 2; k32++) {
            uint32_t kb = k32 * 32 + akof;

            // phase 1: hh
            uint32_t ah[4][4], bh[4][2];
            #pragma unroll
            for (int mi = 0; mi < 4; mi++) {
                uint32_t ra = stb + (uint32_t)(wm * 64 + mi * 16 + arow) * ROWB + kb;
                LDSM4(ah[mi][0], ah[mi][1], ah[mi][2], ah[mi][3], ra + AHI_B);
            }
            #pragma unroll
            for (int nn = 0; nn < 2; nn++) {
                uint32_t rb = stb + (uint32_t)(wn * 32 + nn * 16 + arow) * ROWB + kb;
                uint32_t r0, r1, r2, r3;
                LDSM4(r0, r1, r2, r3, rb + BHI_B);
                bh[2*nn][0] = r0; bh[2*nn][1] = r2;
                bh[2*nn+1][0] = r1; bh[2*nn+1][1] = r3;
            }
            #pragma unroll
            for (int mi = 0; mi < 4; mi++)
                #pragma unroll
                for (int ni = 0; ni < 4; ni++)
                    MMA_S8(acc_h[mi][ni], ah[mi], bh[ni]);

            // phase 2: h * l'
            {
                uint32_t bl[4][2];
                #pragma unroll
                for (int nn = 0; nn < 2; nn++) {
                    uint32_t rb = stb + (uint32_t)(wn * 32 + nn * 16 + arow) * ROWB + kb;
                    uint32_t r0, r1, r2, r3;
                    LDSM4(r0, r1, r2, r3, rb + BLO_B);
                    bl[2*nn][0] = r0; bl[2*nn][1] = r2;
                    bl[2*nn+1][0] = r1; bl[2*nn+1][1] = r3;
                }
                #pragma unroll
                for (int mi = 0; mi < 4; mi++)
                    #pragma unroll
                    for (int ni = 0; ni < 4; ni++)
                        MMA_S8(acc_x[mi][ni], ah[mi], bl[ni]);
            }

            // phase 3: l * h'
            {
                uint32_t al[4][4];
                #pragma unroll
                for (int mi = 0; mi < 4; mi++) {
                    uint32_t ra = stb + (uint32_t)(wm * 64 + mi * 16 + arow) * ROWB + kb;
                    LDSM4(al[mi][0], al[mi][1], al[mi][2], al[mi][3], ra + ALO_B);
                }
                #pragma unroll
                for (int mi = 0; mi < 4; mi++)
                    #pragma unroll
                    for (int ni = 0; ni < 4; ni++)
                        MMA_S8(acc_x[mi][ni], al[mi], bh[ni]);
            }
        }
        __syncthreads();
    }

    // epilogue
    const float inv16129 = 1.0f / 16129.0f;
    const float inv254   = 1.0f / 254.0f;
    const float invSH    = 127.0f / S_H;
    #pragma unroll
    for (int mi = 0; mi < 4; mi++) {
        #pragma unroll
        for (int ni = 0; ni < 4; ni++) {
            int cn = nBase + wn * 32 + ni * 8 + 2 * tig;
            float f0 = Sw[cn]     * inv16129;
            float f1 = Sw[cn + 1] * inv16129;
            float b0 = bias[cn], b1 = bias[cn + 1];
            #pragma unroll
            for (int half = 0; half < 2; half++) {
                int rm = mBase + wm * 64 + mi * 16 + gid + half * 8;
                float sa = Sa ? Sa[rm] : saFixed;
                float v0 = sa * f0 * ((float)acc_h[mi][ni][half*2]   + (float)acc_x[mi][ni][half*2]   * inv254) + b0;
                float v1 = sa * f1 * ((float)acc_h[mi][ni][half*2+1] + (float)acc_x[mi][ni][half*2+1] * inv254) + b1;
                if (EPI == 0) {
                    if (cn < CDIM)     v0 *= 8.0f;
                    if (cn + 1 < CDIM) v1 *= 8.0f;
                    *(float2*)&C[(size_t)rm * N + cn] = make_float2(v0, v1);
                } else if (EPI == 1) {
                    if (rm < M) {
                        float2 r = *(const float2*)&R[(size_t)rm * N + cn];
                        *(float2*)&C[(size_t)rm * N + cn] = make_float2(v0 + r.x, v1 + r.y);
                    }
                } else {
                    v0 = 0.5f * v0 * (1.0f + erff(v0 * 0.70710678118654752f));
                    v1 = 0.5f * v1 * (1.0f + erff(v1 * 0.70710678118654752f));
                    int8_t h0,l0,h1,l1;
                    isplit(v0, invSH, h0, l0);
                    isplit(v1, invSH, h1, l1);
                    char2 hc; hc.x = h0; hc.y = h1;
                    char2 lc; lc.x = l0; lc.y = l1;
                    *(char2*)&Ch[(size_t)rm * N + cn] = hc;
                    *(char2*)&Cl[(size_t)rm * N + cn] = lc;
                }
            }
        }
    }
}

// ---------------------------------------------------------------------------
// Neighbor attention: block per token, warp = head, lane = 2 channels.
// Output int8-split + per-row scale (feeds proj GEMM).
// ---------------------------------------------------------------------------
__global__ void attn_kernel(const float* __restrict__ qkv, const int* __restrict__ which,
                            const int* __restrict__ mask, int8_t* __restrict__ yh,
                            int8_t* __restrict__ yl, float* __restrict__ sa) {
    int t = blockIdx.x;
    int n = t / DEPTH, d = t % DEPTH;
    int h = threadIdx.x >> 5;
    int lane = threadIdx.x & 31;

    float2 q = ((const float2*)(qkv + (size_t)t * (3 * CDIM) + h * HD))[lane];

    float sc[KNB];
    float2 vv[KNB];
    #pragma unroll
    for (int k = 0; k < KNB; k++) {
        int nb = which[n * KNB + k];
        const float* base = qkv + (size_t)(nb * DEPTH + d) * (3 * CDIM) + h * HD;
        float2 kv = ((const float2*)(base + CDIM))[lane];
        vv[k]     = ((const float2*)(base + 2 * CDIM))[lane];
        float dot = q.x * kv.x + q.y * kv.y;
        #pragma unroll
        for (int o = 16; o; o >>= 1) dot += __shfl_xor_sync(0xffffffffu, dot, o);
        sc[k] = (mask[n * KNB + k] > 0) ? dot : -1.0e9f;
    }

    float mx = sc[0];
    #pragma unroll
    for (int k = 1; k < KNB; k++) mx = fmaxf(mx, sc[k]);
    float wsum = 0.0f, w[KNB];
    #pragma unroll
    for (int k = 0; k < KNB; k++) { w[k] = __expf(sc[k] - mx); wsum += w[k]; }
    float inv = 1.0f / wsum;

    float2 acc = make_float2(0.0f, 0.0f);
    #pragma unroll
    for (int k = 0; k < KNB; k++) {
        acc.x += w[k] * vv[k].x;
        acc.y += w[k] * vv[k].y;
    }
    acc.x *= inv; acc.y *= inv;

    float m = fmaxf(fabsf(acc.x), fabsf(acc.y));
    #pragma unroll
    for (int o = 16; o; o >>= 1) m = fmaxf(m, __shfl_xor_sync(0xffffffffu, m, o));
    __shared__ float am[8];
    if (lane == 0) am[h] = m;
    __syncthreads();
    m = am[0];
    #pragma unroll
    for (int i = 1; i < 8; i++) m = fmaxf(m, am[i]);
    float s = fmaxf(m, 1e-20f), qinv = 127.0f / s;

    int8_t h0,l0,h1,l1;
    isplit(acc.x, qinv, h0, l0);
    isplit(acc.y, qinv, h1, l1);
    char2 hc; hc.x = h0; hc.y = h1;
    char2 lc; lc.x = l0; lc.y = l1;
    *(char2*)&yh[(size_t)t * CDIM + h * HD + 2 * lane] = hc;
    *(char2*)&yl[(size_t)t * CDIM + h * HD + 2 * lane] = lc;
    if (threadIdx.x == 0) sa[t] = s;
}

// ---------------------------------------------------------------------------
extern "C" void kernel_launch(void* const* d_in, const int* in_sizes, int n_in,
                              void* d_out, int out_size) {
    const float* x      = (const float*)d_in[0];
    const int*   which  = (const int*)  d_in[1];
    const int*   mask   = (const int*)  d_in[2];
    const float* ln1_w  = (const float*)d_in[3];
    const float* ln1_b  = (const float*)d_in[4];
    const float* qkv_w  = (const float*)d_in[5];
    const float* qkv_b  = (const float*)d_in[6];
    const float* proj_w = (const float*)d_in[7];
    const float* proj_b = (const float*)d_in[8];
    const float* ln2_w  = (const float*)d_in[9];
    const float* ln2_b  = (const float*)d_in[10];
    const float* fc1_w  = (const float*)d_in[11];
    const float* fc1_b  = (const float*)d_in[12];
    const float* fc2_w  = (const float*)d_in[13];
    const float* fc2_b  = (const float*)d_in[14];
    float* out = (float*)d_out;

    float *p_qkv, *p_x2, *p_sa1, *p_sa2;
    int8_t *p_xnh, *p_xnl, *p_yh, *p_yl, *p_hh, *p_hl;
    int8_t *p_wqh, *p_wql, *p_wph, *p_wpl, *p_w1h, *p_w1l, *p_w2h, *p_w2l;
    float *p_swq, *p_swp, *p_sw1, *p_sw2;
    cudaGetSymbolAddress((void**)&p_qkv, g_qkv);
    cudaGetSymbolAddress((void**)&p_x2,  g_x2);
    cudaGetSymbolAddress((void**)&p_sa1, g_sa1);
    cudaGetSymbolAddress((void**)&p_sa2, g_sa2);
    cudaGetSymbolAddress((void**)&p_xnh, g_xn_h);
    cudaGetSymbolAddress((void**)&p_xnl, g_xn_l);
    cudaGetSymbolAddress((void**)&p_yh,  g_y_h);
    cudaGetSymbolAddress((void**)&p_yl,  g_y_l);
    cudaGetSymbolAddress((void**)&p_hh,  g_h_h);
    cudaGetSymbolAddress((void**)&p_hl,  g_h_l);
    cudaGetSymbolAddress((void**)&p_wqh, g_wqkv_h);
    cudaGetSymbolAddress((void**)&p_wql, g_wqkv_l);
    cudaGetSymbolAddress((void**)&p_wph, g_wproj_h);
    cudaGetSymbolAddress((void**)&p_wpl, g_wproj_l);
    cudaGetSymbolAddress((void**)&p_w1h, g_wfc1_h);
    cudaGetSymbolAddress((void**)&p_w1l, g_wfc1_l);
    cudaGetSymbolAddress((void**)&p_w2h, g_wfc2_h);
    cudaGetSymbolAddress((void**)&p_w2l, g_wfc2_l);
    cudaGetSymbolAddress((void**)&p_swq, g_swqkv);
    cudaGetSymbolAddress((void**)&p_swp, g_swproj);
    cudaGetSymbolAddress((void**)&p_sw1, g_swfc1);
    cudaGetSymbolAddress((void**)&p_sw2, g_swfc2);

    cudaFuncSetAttribute(imma_gemm<0>, cudaFuncAttributeMaxDynamicSharedMemorySize, SMEM_BYTES);
    cudaFuncSetAttribute(imma_gemm<1>, cudaFuncAttributeMaxDynamicSharedMemorySize, SMEM_BYTES);
    cudaFuncSetAttribute(imma_gemm<2>, cudaFuncAttributeMaxDynamicSharedMemorySize, SMEM_BYTES);

    // weight quantization (per output row)
    wq_kernel<<<3*CDIM, 128>>>(qkv_w,  p_wqh, p_wql, p_swq, CDIM);
    wq_kernel<<<CDIM,   128>>>(proj_w, p_wph, p_wpl, p_swp, CDIM);
    wq_kernel<<<HIDD,   128>>>(fc1_w,  p_w1h, p_w1l, p_sw1, CDIM);
    wq_kernel<<<CDIM,   128>>>(fc2_w,  p_w2h, p_w2l, p_sw2, HIDD);

    // 1. LN1 -> int8 xn + sa1
    ln_kernel<<<MTOK, 128>>>(x, ln1_w, ln1_b, p_xnh, p_xnl, p_sa1);
    // 2. QKV GEMM (+ q scale) -> fp32 qkv
    imma_gemm<0><<<dim3(MT, 12), 256, SMEM_BYTES>>>(p_xnh, p_xnl, p_wqh, p_wql,
                                                    p_sa1, 0.0f, p_swq, qkv_b,
                                                    nullptr, p_qkv, nullptr, nullptr,
                                                    MTOK, 3 * CDIM, CDIM);
    // 3. attention -> int8 y + sa2
    attn_kernel<<<MTOK, 256>>>(p_qkv, which, mask, p_yh, p_yl, p_sa2);
    // 4. proj + residual(x) -> fp32 x2
    imma_gemm<1><<<dim3(MT, 4), 256, SMEM_BYTES>>>(p_yh, p_yl, p_wph, p_wpl,
                                                   p_sa2, 0.0f, p_swp, proj_b,
                                                   x, p_x2, nullptr, nullptr,
                                                   MTOK, CDIM, CDIM);
    // 5. LN2 -> int8 xn + sa1
    ln_kernel<<<MTOK, 128>>>(p_x2, ln2_w, ln2_b, p_xnh, p_xnl, p_sa1);
    // 6. fc1 + GELU -> int8 h (fixed scale S_H)
    imma_gemm<2><<<dim3(MT, 16), 256, SMEM_BYTES>>>(p_xnh, p_xnl, p_w1h, p_w1l,
                                                    p_sa1, 0.0f, p_sw1, fc1_b,
                                                    nullptr, nullptr, p_hh, p_hl,
                                                    MTOK, HIDD, CDIM);
    // 7. fc2 + residual(x2) -> out  (A scale fixed = S_H)
    imma_gemm<1><<<dim3(MT, 4), 256, SMEM_BYTES>>>(p_hh, p_hl, p_w2h, p_w2l,
                                                   nullptr, S_H, p_sw2, fc2_b,
                                                   p_x2, out, nullptr, nullptr,
                                                   MTOK, CDIM, HIDD);
    (void)in_sizes; (void)n_in; (void)out_size;
}

// round 12
// speedup vs baseline: 3.2997x; 1.1434x over previous
#include <cuda_runtime.h>
#include <math.h>
#include <stdint.h>

#define NVERT 2562
#define DEPTH 8
#define CDIM  512
#define NHEAD 8
#define HD    64
#define KNB   8
#define HIDD  2048
#define MTOK  (NVERT*DEPTH)   /* 20496 */
#define MPAD  20608           /* 161*128 */
#define MT    161

// fp32 scratch
__device__ float g_qkv[(size_t)MPAD*3*CDIM];
__device__ float g_x2 [(size_t)MPAD*CDIM];
// int8 activation planes (hi, lo)
__device__ int8_t g_xn_h[(size_t)MPAD*CDIM];
__device__ int8_t g_xn_l[(size_t)MPAD*CDIM];
__device__ int8_t g_y_h [(size_t)MPAD*CDIM];
__device__ int8_t g_y_l [(size_t)MPAD*CDIM];
__device__ int8_t g_h_h [(size_t)MPAD*HIDD];
__device__ int8_t g_h_l [(size_t)MPAD*HIDD];
// per-row activation scales (zero-init -> padded rows contribute 0)
__device__ float g_sa1[MPAD];
__device__ float g_sa2[MPAD];
// int8 weight planes + per-row scales
__device__ int8_t g_wqkv_h[(size_t)3*CDIM*CDIM];
__device__ int8_t g_wqkv_l[(size_t)3*CDIM*CDIM];
__device__ int8_t g_wproj_h[(size_t)CDIM*CDIM];
__device__ int8_t g_wproj_l[(size_t)CDIM*CDIM];
__device__ int8_t g_wfc1_h[(size_t)HIDD*CDIM];
__device__ int8_t g_wfc1_l[(size_t)HIDD*CDIM];
__device__ int8_t g_wfc2_h[(size_t)CDIM*HIDD];
__device__ int8_t g_wfc2_l[(size_t)CDIM*HIDD];
__device__ float g_swqkv[3*CDIM];
__device__ float g_swproj[CDIM];
__device__ float g_swfc1[HIDD];
__device__ float g_swfc2[CDIM];

#define S_H 6.0f   /* fixed scale for GELU outputs */

// x ~= s/127 * (h + l/254)
__device__ __forceinline__ void isplit(float x, float inv /* =127/s */,
                                       int8_t& h, int8_t& l) {
    float q = fminf(fmaxf(x * inv, -127.0f), 127.0f);
    int hi = __float2int_rn(q);
    int lo = __float2int_rn((q - (float)hi) * 254.0f);
    h = (int8_t)hi; l = (int8_t)lo;
}

// ---------------------------------------------------------------------------
// Weight quantization: one block (128 thr) per output row; per-row scale.
// ---------------------------------------------------------------------------
__global__ void wq_kernel(const float* __restrict__ w, int8_t* __restrict__ h,
                          int8_t* __restrict__ l, float* __restrict__ sw, int K) {
    int row = blockIdx.x, tid = threadIdx.x;
    const float* wr = w + (size_t)row * K;
    float m = 0.0f;
    for (int j = tid; j < K; j += 128) m = fmaxf(m, fabsf(wr[j]));
    #pragma unroll
    for (int o = 16; o; o >>= 1) m = fmaxf(m, __shfl_xor_sync(0xffffffffu, m, o));
    __shared__ float sm4[4];
    if ((tid & 31) == 0) sm4[tid >> 5] = m;
    __syncthreads();
    m = fmaxf(fmaxf(sm4[0], sm4[1]), fmaxf(sm4[2], sm4[3]));
    float s = fmaxf(m, 1e-20f), inv = 127.0f / s;
    if (tid == 0) sw[row] = s;
    for (int j = tid; j < K; j += 128) {
        int8_t hh, ll; isplit(wr[j], inv, hh, ll);
        h[(size_t)row * K + j] = hh;
        l[(size_t)row * K + j] = ll;
    }
}

// ---------------------------------------------------------------------------
// LayerNorm: block (128 thr) per token; int8-split output + per-row scale.
// ---------------------------------------------------------------------------
__global__ void ln_kernel(const float* __restrict__ x, const float* __restrict__ w,
                          const float* __restrict__ b, int8_t* __restrict__ oh,
                          int8_t* __restrict__ ol, float* __restrict__ sa) {
    int t = blockIdx.x;
    const float4* xr = (const float4*)(x + (size_t)t * CDIM);
    float4 v = xr[threadIdx.x];
    float s  = v.x + v.y + v.z + v.w;
    float s2 = v.x*v.x + v.y*v.y + v.z*v.z + v.w*v.w;
    #pragma unroll
    for (int o = 16; o; o >>= 1) {
        s  += __shfl_xor_sync(0xffffffffu, s,  o);
        s2 += __shfl_xor_sync(0xffffffffu, s2, o);
    }
    __shared__ float ss[4], ssq[4], smx[4];
    int wid = threadIdx.x >> 5, lane = threadIdx.x & 31;
    if (lane == 0) { ss[wid] = s; ssq[wid] = s2; }
    __syncthreads();
    s  = ss[0] + ss[1] + ss[2] + ss[3];
    s2 = ssq[0] + ssq[1] + ssq[2] + ssq[3];
    float mean = s * (1.0f / CDIM);
    float var  = s2 * (1.0f / CDIM) - mean * mean;
    float rstd = rsqrtf(var + 1e-5f);
    float4 wv = ((const float4*)w)[threadIdx.x];
    float4 bv = ((const float4*)b)[threadIdx.x];
    float o0 = (v.x - mean) * rstd * wv.x + bv.x;
    float o1 = (v.y - mean) * rstd * wv.y + bv.y;
    float o2 = (v.z - mean) * rstd * wv.z + bv.z;
    float o3 = (v.w - mean) * rstd * wv.w + bv.w;
    float mx = fmaxf(fmaxf(fabsf(o0), fabsf(o1)), fmaxf(fabsf(o2), fabsf(o3)));
    #pragma unroll
    for (int o = 16; o; o >>= 1) mx = fmaxf(mx, __shfl_xor_sync(0xffffffffu, mx, o));
    if (lane == 0) smx[wid] = mx;
    __syncthreads();
    mx = fmaxf(fmaxf(smx[0], smx[1]), fmaxf(smx[2], smx[3]));
    float sc = fmaxf(mx, 1e-20f), inv = 127.0f / sc;
    int8_t h0,l0,h1,l1,h2,l2,h3,l3;
    isplit(o0, inv, h0, l0); isplit(o1, inv, h1, l1);
    isplit(o2, inv, h2, l2); isplit(o3, inv, h3, l3);
    char4 hc; hc.x=h0; hc.y=h1; hc.z=h2; hc.w=h3;
    char4 lc; lc.x=l0; lc.y=l1; lc.z=l2; lc.w=l3;
    ((char4*)(oh + (size_t)t * CDIM))[threadIdx.x] = hc;
    ((char4*)(ol + (size_t)t * CDIM))[threadIdx.x] = lc;
    if (threadIdx.x == 0) sa[t] = sc;
}

// ---------------------------------------------------------------------------
// Split-int8 IMMA GEMM: C = A @ W^T with A,W each 2-plane int8.
// acc_hh and acc_cross in int32 (exact); C = sa*sw/16129*(hh + cross/254).
// CTA tile 128(M)x64(N), stage depth 64 int8, double-buffered cp.async,
// 8 warps 4x2 (32x32 warp tile) -> 64 persistent acc regs/thread, so
// __launch_bounds__(256,2) holds 2 CTAs/SM (4 warps/SMSP).
// EPI: 0 = bias + q-scale -> fp32 C
//      1 = bias + residual R -> fp32 C (guard m<M)
//      2 = bias + exact GELU -> int8-split (Ch, Cl) with fixed scale S_H
// ---------------------------------------------------------------------------
#define ROWB 80
#define AROWS 128
#define BROWS 64
#define APL (AROWS*ROWB)             /* 10240 */
#define BPL (BROWS*ROWB)             /* 5120 */
#define AHI_B 0
#define ALO_B APL
#define BHI_B (2*APL)
#define BLO_B (2*APL + BPL)
#define STAGE_B (2*APL + 2*BPL)      /* 30720 */
#define SMEM_BYTES (2*STAGE_B)       /* 61440 */

__device__ __forceinline__ void cp_async16(uint32_t dst, const void* src) {
    asm volatile("cp.async.cg.shared.global [%0], [%1], 16;\n" :: "r"(dst), "l"(src));
}
#define LDSM4(r0,r1,r2,r3,addr) \
    asm volatile("ldmatrix.sync.aligned.m8n8.x4.shared.b16 {%0,%1,%2,%3}, [%4];" \
                 : "=r"(r0),"=r"(r1),"=r"(r2),"=r"(r3) : "r"(addr))
#define MMA_S8(c, a, b) \
    asm volatile("mma.sync.aligned.m16n8k32.row.col.satfinite.s32.s8.s8.s32 " \
                 "{%0,%1,%2,%3}, {%4,%5,%6,%7}, {%8,%9}, {%0,%1,%2,%3};\n" \
                 : "+r"((c)[0]), "+r"((c)[1]), "+r"((c)[2]), "+r"((c)[3]) \
                 : "r"((a)[0]), "r"((a)[1]), "r"((a)[2]), "r"((a)[3]), \
                   "r"((b)[0]), "r"((b)[1]))

template<int EPI>
__global__ void __launch_bounds__(256, 2)
imma_gemm(const int8_t* __restrict__ Ah, const int8_t* __restrict__ Al,
          const int8_t* __restrict__ Wh, const int8_t* __restrict__ Wl,
          const float* __restrict__ Sa, float saFixed,
          const float* __restrict__ Sw,
          const float* __restrict__ bias, const float* __restrict__ R,
          float* __restrict__ C, int8_t* __restrict__ Ch, int8_t* __restrict__ Cl,
          int M, int N, int K) {
    extern __shared__ char sm[];
    uint32_t sb = (uint32_t)__cvta_generic_to_shared(sm);

    const int tid   = threadIdx.x;
    const int lane  = tid & 31;
    const int wid   = tid >> 5;
    const int wm    = wid >> 1;              // 0..3 -> 32-row strip
    const int wn    = wid & 1;               // 0..1 -> 32-col strip
    const int gid   = lane >> 2;
    const int tig   = lane & 3;
    const int mBase = blockIdx.x * 128;
    const int nBase = blockIdx.y * 64;
    const int nk    = K >> 6;                // stages of 64 int8

    // A loader: 2 chunks/thread; B loader: 1 chunk/thread
    const int lrow = tid >> 1;
    const int lcc  = (tid & 1) * 2;
    const int brow = tid >> 2;
    const int bch  = tid & 3;

    const int lg = lane >> 3;
    const int lr = lane & 7;
    const int arow = lr + (lg & 1) * 8;
    const int akof = (lg >> 1) * 16;

    int acc_h[2][4][4], acc_x[2][4][4];
    #pragma unroll
    for (int mi = 0; mi < 2; mi++)
        #pragma unroll
        for (int ni = 0; ni < 4; ni++)
            #pragma unroll
            for (int c = 0; c < 4; c++) { acc_h[mi][ni][c] = 0; acc_x[mi][ni][c] = 0; }

    auto stage_load = [&](int kt, int st) {
        int k0 = kt * 64;
        size_t ga = (size_t)(mBase + lrow) * K + k0 + lcc * 16;
        size_t gb = (size_t)(nBase + brow) * K + k0 + bch * 16;
        uint32_t da = sb + st * STAGE_B + lrow * ROWB + lcc * 16;
        uint32_t db = sb + st * STAGE_B + brow * ROWB + bch * 16;
        cp_async16(da + AHI_B,      Ah + ga);
        cp_async16(da + AHI_B + 16, Ah + ga + 16);
        cp_async16(da + ALO_B,      Al + ga);
        cp_async16(da + ALO_B + 16, Al + ga + 16);
        cp_async16(db + BHI_B,      Wh + gb);
        cp_async16(db + BLO_B,      Wl + gb);
        asm volatile("cp.async.commit_group;\n");
    };

    stage_load(0, 0);

    for (int kt = 0; kt < nk; kt++) {
        int st = kt & 1;
        if (kt + 1 < nk) {
            stage_load(kt + 1, (kt + 1) & 1);
            asm volatile("cp.async.wait_group 1;\n");
        } else {
            asm volatile("cp.async.wait_group 0;\n");
        }
        __syncthreads();

        uint32_t stb = sb + st * STAGE_B;

        #pragma unroll
        for (int k32 = 0; k32 < 2; k32++) {
            uint32_t kb = k32 * 32 + akof;

            // phase 1: hh
            uint32_t ah[2][4], bh[4][2];
            #pragma unroll
            for (int mi = 0; mi < 2; mi++) {
                uint32_t ra = stb + (uint32_t)(wm * 32 + mi * 16 + arow) * ROWB + kb;
                LDSM4(ah[mi][0], ah[mi][1], ah[mi][2], ah[mi][3], ra + AHI_B);
            }
            #pragma unroll
            for (int nn = 0; nn < 2; nn++) {
                uint32_t rb = stb + (uint32_t)(wn * 32 + nn * 16 + arow) * ROWB + kb;
                uint32_t r0, r1, r2, r3;
                LDSM4(r0, r1, r2, r3, rb + BHI_B);
                bh[2*nn][0] = r0; bh[2*nn][1] = r2;
                bh[2*nn+1][0] = r1; bh[2*nn+1][1] = r3;
            }
            #pragma unroll
            for (int mi = 0; mi < 2; mi++)
                #pragma unroll
                for (int ni = 0; ni < 4; ni++)
                    MMA_S8(acc_h[mi][ni], ah[mi], bh[ni]);

            // phase 2: h * l'
            {
                uint32_t bl[4][2];
                #pragma unroll
                for (int nn = 0; nn < 2; nn++) {
                    uint32_t rb = stb + (uint32_t)(wn * 32 + nn * 16 + arow) * ROWB + kb;
                    uint32_t r0, r1, r2, r3;
                    LDSM4(r0, r1, r2, r3, rb + BLO_B);
                    bl[2*nn][0] = r0; bl[2*nn][1] = r2;
                    bl[2*nn+1][0] = r1; bl[2*nn+1][1] = r3;
                }
                #pragma unroll
                for (int mi = 0; mi < 2; mi++)
                    #pragma unroll
                    for (int ni = 0; ni < 4; ni++)
                        MMA_S8(acc_x[mi][ni], ah[mi], bl[ni]);
            }

            // phase 3: l * h'
            {
                uint32_t al[2][4];
                #pragma unroll
                for (int mi = 0; mi < 2; mi++) {
                    uint32_t ra = stb + (uint32_t)(wm * 32 + mi * 16 + arow) * ROWB + kb;
                    LDSM4(al[mi][0], al[mi][1], al[mi][2], al[mi][3], ra + ALO_B);
                }
                #pragma unroll
                for (int mi = 0; mi < 2; mi++)
                    #pragma unroll
                    for (int ni = 0; ni < 4; ni++)
                        MMA_S8(acc_x[mi][ni], al[mi], bh[ni]);
            }
        }
        __syncthreads();
    }

    // epilogue
    const float inv16129 = 1.0f / 16129.0f;
    const float inv254   = 1.0f / 254.0f;
    const float invSH    = 127.0f / S_H;
    #pragma unroll
    for (int mi = 0; mi < 2; mi++) {
        #pragma unroll
        for (int ni = 0; ni < 4; ni++) {
            int cn = nBase + wn * 32 + ni * 8 + 2 * tig;
            float f0 = Sw[cn]     * inv16129;
            float f1 = Sw[cn + 1] * inv16129;
            float b0 = bias[cn], b1 = bias[cn + 1];
            #pragma unroll
            for (int half = 0; half < 2; half++) {
                int rm = mBase + wm * 32 + mi * 16 + gid + half * 8;
                float sa = Sa ? Sa[rm] : saFixed;
                float v0 = sa * f0 * ((float)acc_h[mi][ni][half*2]   + (float)acc_x[mi][ni][half*2]   * inv254) + b0;
                float v1 = sa * f1 * ((float)acc_h[mi][ni][half*2+1] + (float)acc_x[mi][ni][half*2+1] * inv254) + b1;
                if (EPI == 0) {
                    if (cn < CDIM)     v0 *= 8.0f;
                    if (cn + 1 < CDIM) v1 *= 8.0f;
                    *(float2*)&C[(size_t)rm * N + cn] = make_float2(v0, v1);
                } else if (EPI == 1) {
                    if (rm < M) {
                        float2 r = *(const float2*)&R[(size_t)rm * N + cn];
                        *(float2*)&C[(size_t)rm * N + cn] = make_float2(v0 + r.x, v1 + r.y);
                    }
                } else {
                    v0 = 0.5f * v0 * (1.0f + erff(v0 * 0.70710678118654752f));
                    v1 = 0.5f * v1 * (1.0f + erff(v1 * 0.70710678118654752f));
                    int8_t h0,l0,h1,l1;
                    isplit(v0, invSH, h0, l0);
                    isplit(v1, invSH, h1, l1);
                    char2 hc; hc.x = h0; hc.y = h1;
                    char2 lc; lc.x = l0; lc.y = l1;
                    *(char2*)&Ch[(size_t)rm * N + cn] = hc;
                    *(char2*)&Cl[(size_t)rm * N + cn] = lc;
                }
            }
        }
    }
}

// ---------------------------------------------------------------------------
// Neighbor attention: block per token, warp = head, lane = 2 channels.
// Output int8-split + per-row scale (feeds proj GEMM).
// ---------------------------------------------------------------------------
__global__ void attn_kernel(const float* __restrict__ qkv, const int* __restrict__ which,
                            const int* __restrict__ mask, int8_t* __restrict__ yh,
                            int8_t* __restrict__ yl, float* __restrict__ sa) {
    int t = blockIdx.x;
    int n = t / DEPTH, d = t % DEPTH;
    int h = threadIdx.x >> 5;
    int lane = threadIdx.x & 31;

    float2 q = ((const float2*)(qkv + (size_t)t * (3 * CDIM) + h * HD))[lane];

    float sc[KNB];
    float2 vv[KNB];
    #pragma unroll
    for (int k = 0; k < KNB; k++) {
        int nb = which[n * KNB + k];
        const float* base = qkv + (size_t)(nb * DEPTH + d) * (3 * CDIM) + h * HD;
        float2 kv = ((const float2*)(base + CDIM))[lane];
        vv[k]     = ((const float2*)(base + 2 * CDIM))[lane];
        float dot = q.x * kv.x + q.y * kv.y;
        #pragma unroll
        for (int o = 16; o; o >>= 1) dot += __shfl_xor_sync(0xffffffffu, dot, o);
        sc[k] = (mask[n * KNB + k] > 0) ? dot : -1.0e9f;
    }

    float mx = sc[0];
    #pragma unroll
    for (int k = 1; k < KNB; k++) mx = fmaxf(mx, sc[k]);
    float wsum = 0.0f, w[KNB];
    #pragma unroll
    for (int k = 0; k < KNB; k++) { w[k] = __expf(sc[k] - mx); wsum += w[k]; }
    float inv = 1.0f / wsum;

    float2 acc = make_float2(0.0f, 0.0f);
    #pragma unroll
    for (int k = 0; k < KNB; k++) {
        acc.x += w[k] * vv[k].x;
        acc.y += w[k] * vv[k].y;
    }
    acc.x *= inv; acc.y *= inv;

    float m = fmaxf(fabsf(acc.x), fabsf(acc.y));
    #pragma unroll
    for (int o = 16; o; o >>= 1) m = fmaxf(m, __shfl_xor_sync(0xffffffffu, m, o));
    __shared__ float am[8];
    if (lane == 0) am[h] = m;
    __syncthreads();
    m = am[0];
    #pragma unroll
    for (int i = 1; i < 8; i++) m = fmaxf(m, am[i]);
    float s = fmaxf(m, 1e-20f), qinv = 127.0f / s;

    int8_t h0,l0,h1,l1;
    isplit(acc.x, qinv, h0, l0);
    isplit(acc.y, qinv, h1, l1);
    char2 hc; hc.x = h0; hc.y = h1;
    char2 lc; lc.x = l0; lc.y = l1;
    *(char2*)&yh[(size_t)t * CDIM + h * HD + 2 * lane] = hc;
    *(char2*)&yl[(size_t)t * CDIM + h * HD + 2 * lane] = lc;
    if (threadIdx.x == 0) sa[t] = s;
}

// ---------------------------------------------------------------------------
extern "C" void kernel_launch(void* const* d_in, const int* in_sizes, int n_in,
                              void* d_out, int out_size) {
    const float* x      = (const float*)d_in[0];
    const int*   which  = (const int*)  d_in[1];
    const int*   mask   = (const int*)  d_in[2];
    const float* ln1_w  = (const float*)d_in[3];
    const float* ln1_b  = (const float*)d_in[4];
    const float* qkv_w  = (const float*)d_in[5];
    const float* qkv_b  = (const float*)d_in[6];
    const float* proj_w = (const float*)d_in[7];
    const float* proj_b = (const float*)d_in[8];
    const float* ln2_w  = (const float*)d_in[9];
    const float* ln2_b  = (const float*)d_in[10];
    const float* fc1_w  = (const float*)d_in[11];
    const float* fc1_b  = (const float*)d_in[12];
    const float* fc2_w  = (const float*)d_in[13];
    const float* fc2_b  = (const float*)d_in[14];
    float* out = (float*)d_out;

    float *p_qkv, *p_x2, *p_sa1, *p_sa2;
    int8_t *p_xnh, *p_xnl, *p_yh, *p_yl, *p_hh, *p_hl;
    int8_t *p_wqh, *p_wql, *p_wph, *p_wpl, *p_w1h, *p_w1l, *p_w2h, *p_w2l;
    float *p_swq, *p_swp, *p_sw1, *p_sw2;
    cudaGetSymbolAddress((void**)&p_qkv, g_qkv);
    cudaGetSymbolAddress((void**)&p_x2,  g_x2);
    cudaGetSymbolAddress((void**)&p_sa1, g_sa1);
    cudaGetSymbolAddress((void**)&p_sa2, g_sa2);
    cudaGetSymbolAddress((void**)&p_xnh, g_xn_h);
    cudaGetSymbolAddress((void**)&p_xnl, g_xn_l);
    cudaGetSymbolAddress((void**)&p_yh,  g_y_h);
    cudaGetSymbolAddress((void**)&p_yl,  g_y_l);
    cudaGetSymbolAddress((void**)&p_hh,  g_h_h);
    cudaGetSymbolAddress((void**)&p_hl,  g_h_l);
    cudaGetSymbolAddress((void**)&p_wqh, g_wqkv_h);
    cudaGetSymbolAddress((void**)&p_wql, g_wqkv_l);
    cudaGetSymbolAddress((void**)&p_wph, g_wproj_h);
    cudaGetSymbolAddress((void**)&p_wpl, g_wproj_l);
    cudaGetSymbolAddress((void**)&p_w1h, g_wfc1_h);
    cudaGetSymbolAddress((void**)&p_w1l, g_wfc1_l);
    cudaGetSymbolAddress((void**)&p_w2h, g_wfc2_h);
    cudaGetSymbolAddress((void**)&p_w2l, g_wfc2_l);
    cudaGetSymbolAddress((void**)&p_swq, g_swqkv);
    cudaGetSymbolAddress((void**)&p_swp, g_swproj);
    cudaGetSymbolAddress((void**)&p_sw1, g_swfc1);
    cudaGetSymbolAddress((void**)&p_sw2, g_swfc2);

    cudaFuncSetAttribute(imma_gemm<0>, cudaFuncAttributeMaxDynamicSharedMemorySize, SMEM_BYTES);
    cudaFuncSetAttribute(imma_gemm<1>, cudaFuncAttributeMaxDynamicSharedMemorySize, SMEM_BYTES);
    cudaFuncSetAttribute(imma_gemm<2>, cudaFuncAttributeMaxDynamicSharedMemorySize, SMEM_BYTES);

    // weight quantization (per output row)
    wq_kernel<<<3*CDIM, 128>>>(qkv_w,  p_wqh, p_wql, p_swq, CDIM);
    wq_kernel<<<CDIM,   128>>>(proj_w, p_wph, p_wpl, p_swp, CDIM);
    wq_kernel<<<HIDD,   128>>>(fc1_w,  p_w1h, p_w1l, p_sw1, CDIM);
    wq_kernel<<<CDIM,   128>>>(fc2_w,  p_w2h, p_w2l, p_sw2, HIDD);

    // 1. LN1 -> int8 xn + sa1
    ln_kernel<<<MTOK, 128>>>(x, ln1_w, ln1_b, p_xnh, p_xnl, p_sa1);
    // 2. QKV GEMM (+ q scale) -> fp32 qkv   (N tiles of 64)
    imma_gemm<0><<<dim3(MT, 24), 256, SMEM_BYTES>>>(p_xnh, p_xnl, p_wqh, p_wql,
                                                    p_sa1, 0.0f, p_swq, qkv_b,
                                                    nullptr, p_qkv, nullptr, nullptr,
                                                    MTOK, 3 * CDIM, CDIM);
    // 3. attention -> int8 y + sa2
    attn_kernel<<<MTOK, 256>>>(p_qkv, which, mask, p_yh, p_yl, p_sa2);
    // 4. proj + residual(x) -> fp32 x2
    imma_gemm<1><<<dim3(MT, 8), 256, SMEM_BYTES>>>(p_yh, p_yl, p_wph, p_wpl,
                                                   p_sa2, 0.0f, p_swp, proj_b,
                                                   x, p_x2, nullptr, nullptr,
                                                   MTOK, CDIM, CDIM);
    // 5. LN2 -> int8 xn + sa1
    ln_kernel<<<MTOK, 128>>>(p_x2, ln2_w, ln2_b, p_xnh, p_xnl, p_sa1);
    // 6. fc1 + GELU -> int8 h (fixed scale S_H)
    imma_gemm<2><<<dim3(MT, 32), 256, SMEM_BYTES>>>(p_xnh, p_xnl, p_w1h, p_w1l,
                                                    p_sa1, 0.0f, p_sw1, fc1_b,
                                                    nullptr, nullptr, p_hh, p_hl,
                                                    MTOK, HIDD, CDIM);
    // 7. fc2 + residual(x2) -> out  (A scale fixed = S_H)
    imma_gemm<1><<<dim3(MT, 8), 256, SMEM_BYTES>>>(p_hh, p_hl, p_w2h, p_w2l,
                                                   nullptr, S_H, p_sw2, fc2_b,
                                                   p_x2, out, nullptr, nullptr,
                                                   MTOK, CDIM, HIDD);
    (void)in_sizes; (void)n_in; (void)out_size;
}